// round 12
// baseline (speedup 1.0000x reference)
#include <cuda_runtime.h>
#include <cuda_fp16.h>
#include <cstdint>
#include <math.h>

// Problem constants (fixed shapes for this registry entry)
#define NMAX 32768
#define GMAX 2048
#define EMAX 1146880

// Scratch (no cudaMalloc allowed)
__device__ __half  g_h[NMAX * 64];         // node embeddings fp16 [N,64] (4 MB)
__device__ float2  g_segmr[GMAX * 64];     // per-graph per-feature (max, 1/sum)
__device__ __half  g_xh[(size_t)EMAX * 64];// hyperedge features, fp16 (147 MB)

// ---------------------------------------------------------------------------
// PTX wrappers (portable tensor path: ldmatrix + mma.sync, compute_103-safe)
// ---------------------------------------------------------------------------
__device__ __forceinline__ uint32_t smem_u32(const void* p) {
    uint32_t a;
    asm("{ .reg .u64 t; cvta.to.shared.u64 t, %1; cvt.u32.u64 %0, t; }" : "=r"(a) : "l"(p));
    return a;
}
__device__ __forceinline__ void ldsm4(uint32_t& r0, uint32_t& r1, uint32_t& r2, uint32_t& r3,
                                      uint32_t addr) {
    asm volatile("ldmatrix.sync.aligned.m8n8.x4.shared.b16 {%0,%1,%2,%3}, [%4];"
                 : "=r"(r0), "=r"(r1), "=r"(r2), "=r"(r3) : "r"(addr));
}
__device__ __forceinline__ void mma_f16(float d[4], uint32_t a0, uint32_t a1, uint32_t a2,
                                        uint32_t a3, uint32_t b0, uint32_t b1) {
    asm volatile(
        "mma.sync.aligned.m16n8k16.row.col.f32.f16.f16.f32 "
        "{%0,%1,%2,%3},{%4,%5,%6,%7},{%8,%9},{%0,%1,%2,%3};"
        : "+f"(d[0]), "+f"(d[1]), "+f"(d[2]), "+f"(d[3])
        : "r"(a0), "r"(a1), "r"(a2), "r"(a3), "r"(b0), "r"(b1));
}
__device__ __forceinline__ uint32_t pack_h2(float lo, float hi) {
    uint32_t r;
    asm("cvt.rn.f16x2.f32 %0, %1, %2;" : "=r"(r) : "f"(hi), "f"(lo));
    return r;
}
__device__ __forceinline__ void h2x4_to_f8(uint4 v, float* x) {
    float2 t;
    t = __half22float2(*(__half2*)&v.x); x[0] = t.x; x[1] = t.y;
    t = __half22float2(*(__half2*)&v.y); x[2] = t.x; x[3] = t.y;
    t = __half22float2(*(__half2*)&v.z); x[4] = t.x; x[5] = t.y;
    t = __half22float2(*(__half2*)&v.w); x[6] = t.x; x[7] = t.y;
}

// ---------------------------------------------------------------------------
// K1: node MLP via fp16 MMA (unchanged from R10).
// ---------------------------------------------------------------------------
#define K1_W1   0
#define K1_W2   8192
#define K1_W3   16384
#define K1_B1   24576
#define K1_B2   24832
#define K1_B3   25088
#define K1_IN   25344
#define K1_SMEM (K1_IN + 8 * 2048)   // 41728

__global__ __launch_bounds__(256)
void k_node_mlp_mma(const float* __restrict__ x, const float* __restrict__ u,
                    const int* __restrict__ batch,
                    const float* __restrict__ W1, const float* __restrict__ b1,
                    const float* __restrict__ W2, const float* __restrict__ b2,
                    const float* __restrict__ W3, const float* __restrict__ b3,
                    int n)
{
    extern __shared__ __align__(128) char smem[];
    uint32_t sb = smem_u32(smem);
    int tid = threadIdx.x;

    for (int i = tid; i < 64 * 16; i += 256) {
        int nn = i >> 4, k = i & 15;
        uint32_t off = (uint32_t)nn * 128 + (((uint32_t)k * 2) ^ (((uint32_t)nn & 7) * 16));
        *(__half*)(smem + K1_W1 + off) = __float2half(W1[k * 64 + nn]);
    }
    for (int i = tid; i < 64 * 64; i += 256) {
        int nn = i >> 6, k = i & 63;
        uint32_t off = (uint32_t)nn * 128 + (((uint32_t)k * 2) ^ (((uint32_t)nn & 7) * 16));
        *(__half*)(smem + K1_W2 + off) = __float2half(W2[k * 64 + nn]);
        *(__half*)(smem + K1_W3 + off) = __float2half(W3[k * 64 + nn]);
    }
    for (int i = tid; i < 64; i += 256) {
        ((float*)(smem + K1_B1))[i] = b1[i];
        ((float*)(smem + K1_B2))[i] = b2[i];
        ((float*)(smem + K1_B3))[i] = b3[i];
    }
    __syncthreads();

    const float* sB1 = (const float*)(smem + K1_B1);
    const float* sB2 = (const float*)(smem + K1_B2);
    const float* sB3 = (const float*)(smem + K1_B3);

    int warp = tid >> 5, lane = tid & 31;
    char* sin = smem + K1_IN + warp * 2048;
    uint32_t sin_u = sb + K1_IN + (uint32_t)warp * 2048;

    int node0 = (blockIdx.x * 8 + warp) * 16;

    {
        int r = lane >> 1;
        int halfc = lane & 1;
        int nd = node0 + r;
        uint32_t off = (uint32_t)r * 128 + (((uint32_t)halfc * 16) ^ (((uint32_t)(r & 7)) * 16));
        uint4 v = make_uint4(0, 0, 0, 0);
        if (nd < n) {
            int b = __ldg(batch + nd);
            if (halfc == 0) {
                float2 a0 = *(const float2*)(x + (size_t)nd * 6);
                float2 a1 = *(const float2*)(x + (size_t)nd * 6 + 2);
                float2 a2 = *(const float2*)(x + (size_t)nd * 6 + 4);
                float2 u0 = *(const float2*)(u + (size_t)b * 4);
                v.x = pack_h2(a0.x, a0.y);
                v.y = pack_h2(a1.x, a1.y);
                v.z = pack_h2(a2.x, a2.y);
                v.w = pack_h2(u0.x, u0.y);
            } else {
                float2 u1 = *(const float2*)(u + (size_t)b * 4 + 2);
                v.x = pack_h2(u1.x, u1.y);
            }
        }
        *(uint4*)(sin + off) = v;
    }
    __syncwarp();

    int rowA = lane & 15;
    uint32_t aKx  = ((uint32_t)(lane >> 4)) * 16;
    uint32_t aXor = ((uint32_t)(rowA & 7)) * 16;
    int rowB = (lane & 7) + ((lane >> 4) & 1) * 8;
    uint32_t bKx  = ((uint32_t)((lane >> 3) & 1)) * 16;
    uint32_t bXor = ((uint32_t)(lane & 7)) * 16;
    int qr = lane >> 2;
    int qc = lane & 3;

    float d[8][4];
    uint32_t ax[4][4];

#pragma unroll
    for (int j = 0; j < 8; j++) { d[j][0] = 0.f; d[j][1] = 0.f; d[j][2] = 0.f; d[j][3] = 0.f; }
    {
        uint32_t a0, a1, a2, a3;
        ldsm4(a0, a1, a2, a3, sin_u + (uint32_t)rowA * 128 + (aKx ^ aXor));
#pragma unroll
        for (int jt = 0; jt < 4; jt++) {
            uint32_t b0, b1r, b2r, b3r;
            uint32_t baddr = sb + K1_W1 + (uint32_t)(jt * 16 + rowB) * 128 + (bKx ^ bXor);
            ldsm4(b0, b1r, b2r, b3r, baddr);
            mma_f16(d[2 * jt],     a0, a1, a2, a3, b0, b1r);
            mma_f16(d[2 * jt + 1], a0, a1, a2, a3, b2r, b3r);
        }
    }
#pragma unroll
    for (int kt = 0; kt < 4; kt++) {
        int j0 = 2 * kt, j1 = j0 + 1;
        float2 bv0 = *(const float2*)(sB1 + j0 * 8 + qc * 2);
        float2 bv1 = *(const float2*)(sB1 + j1 * 8 + qc * 2);
        ax[kt][0] = pack_h2(fmaxf(d[j0][0] + bv0.x, 0.f), fmaxf(d[j0][1] + bv0.y, 0.f));
        ax[kt][1] = pack_h2(fmaxf(d[j0][2] + bv0.x, 0.f), fmaxf(d[j0][3] + bv0.y, 0.f));
        ax[kt][2] = pack_h2(fmaxf(d[j1][0] + bv1.x, 0.f), fmaxf(d[j1][1] + bv1.y, 0.f));
        ax[kt][3] = pack_h2(fmaxf(d[j1][2] + bv1.x, 0.f), fmaxf(d[j1][3] + bv1.y, 0.f));
    }

#pragma unroll
    for (int j = 0; j < 8; j++) { d[j][0] = 0.f; d[j][1] = 0.f; d[j][2] = 0.f; d[j][3] = 0.f; }
#pragma unroll
    for (int kt = 0; kt < 4; kt++) {
#pragma unroll
        for (int jt = 0; jt < 4; jt++) {
            uint32_t b0, b1r, b2r, b3r;
            uint32_t baddr = sb + K1_W2 + (uint32_t)(jt * 16 + rowB) * 128
                           + (((uint32_t)kt * 32 + bKx) ^ bXor);
            ldsm4(b0, b1r, b2r, b3r, baddr);
            mma_f16(d[2 * jt],     ax[kt][0], ax[kt][1], ax[kt][2], ax[kt][3], b0, b1r);
            mma_f16(d[2 * jt + 1], ax[kt][0], ax[kt][1], ax[kt][2], ax[kt][3], b2r, b3r);
        }
    }
#pragma unroll
    for (int kt = 0; kt < 4; kt++) {
        int j0 = 2 * kt, j1 = j0 + 1;
        float2 bv0 = *(const float2*)(sB2 + j0 * 8 + qc * 2);
        float2 bv1 = *(const float2*)(sB2 + j1 * 8 + qc * 2);
        ax[kt][0] = pack_h2(fmaxf(d[j0][0] + bv0.x, 0.f), fmaxf(d[j0][1] + bv0.y, 0.f));
        ax[kt][1] = pack_h2(fmaxf(d[j0][2] + bv0.x, 0.f), fmaxf(d[j0][3] + bv0.y, 0.f));
        ax[kt][2] = pack_h2(fmaxf(d[j1][0] + bv1.x, 0.f), fmaxf(d[j1][1] + bv1.y, 0.f));
        ax[kt][3] = pack_h2(fmaxf(d[j1][2] + bv1.x, 0.f), fmaxf(d[j1][3] + bv1.y, 0.f));
    }

#pragma unroll
    for (int j = 0; j < 8; j++) { d[j][0] = 0.f; d[j][1] = 0.f; d[j][2] = 0.f; d[j][3] = 0.f; }
#pragma unroll
    for (int kt = 0; kt < 4; kt++) {
#pragma unroll
        for (int jt = 0; jt < 4; jt++) {
            uint32_t b0, b1r, b2r, b3r;
            uint32_t baddr = sb + K1_W3 + (uint32_t)(jt * 16 + rowB) * 128
                           + (((uint32_t)kt * 32 + bKx) ^ bXor);
            ldsm4(b0, b1r, b2r, b3r, baddr);
            mma_f16(d[2 * jt],     ax[kt][0], ax[kt][1], ax[kt][2], ax[kt][3], b0, b1r);
            mma_f16(d[2 * jt + 1], ax[kt][0], ax[kt][1], ax[kt][2], ax[kt][3], b2r, b3r);
        }
    }
    {
        __half2* Gh2 = (__half2*)g_h;
        int na = node0 + qr, nb = node0 + qr + 8;
#pragma unroll
        for (int j = 0; j < 8; j++) {
            float2 bv = *(const float2*)(sB3 + j * 8 + qc * 2);
            int fp = j * 4 + qc;
            if (na < n)
                Gh2[(size_t)na * 32 + fp] = __floats2half2_rn(d[j][0] + bv.x, d[j][1] + bv.y);
            if (nb < n)
                Gh2[(size_t)nb * 32 + fp] = __floats2half2_rn(d[j][2] + bv.x, d[j][3] + bv.y);
        }
    }
}

// ---------------------------------------------------------------------------
// K2: segment softmax stats + x_hyper materialization, 2-deep pipelined:
// indices prefetched 1 iter ahead of their gathers; gathers issued 1 iter
// ahead of their compute. Each lane keeps 3 gathers + 3 idx loads in flight.
// ---------------------------------------------------------------------------
__device__ __forceinline__ int lbound(const int* __restrict__ a, int n, int key)
{
    int lo = 0, hi = n;
    while (lo < hi) { int mid = (lo + hi) >> 1; if (a[mid] < key) lo = mid + 1; else hi = mid; }
    return lo;
}

__global__ __launch_bounds__(512)
void k_segstats(const int* __restrict__ hidx, const int* __restrict__ bh, int E,
                float* __restrict__ out, int writeBatch)
{
    __shared__ float sm_m[64][64];
    __shared__ float sm_s[64][64];

    int g = blockIdx.x;
    int lo = lbound(bh, E, g);
    int hi = lbound(bh, E, g + 1);

    int tid = threadIdx.x;
    int w = tid >> 5, lane = tid & 31;
    int j = lane >> 3;       // edge slot within warp (0..3)
    int c = lane & 7;        // 16B chunk (features c*8 .. c*8+7)

    const uint4* H4 = (const uint4*)g_h;
    uint4* XH4 = (uint4*)g_xh;

    float m[8], s[8];
#pragma unroll
    for (int q = 0; q < 8; q++) { m[q] = -3.0e38f; s[q] = 0.f; }

    int e = lo + w * 4 + j;

    // pipeline state: gathers for edge e in registers; indices for e+64
    uint4 va = make_uint4(0,0,0,0), vb = va, vc = va;
    int n0 = 0, n1 = 0, n2 = 0;
    if (e < hi) {
        int i0 = __ldg(hidx + e), i1 = __ldg(hidx + E + e), i2 = __ldg(hidx + 2 * E + e);
        va = H4[i0 * 8 + c]; vb = H4[i1 * 8 + c]; vc = H4[i2 * 8 + c];
        int en = e + 64;
        if (en < hi) {
            n0 = __ldg(hidx + en); n1 = __ldg(hidx + E + en); n2 = __ldg(hidx + 2 * E + en);
        }
    }

    while (e < hi) {
        int en = e + 64;
        // issue gathers for e+64 (indices prefetched last iteration)
        uint4 wa, wb2, wc;
        if (en < hi) {
            wa = H4[n0 * 8 + c]; wb2 = H4[n1 * 8 + c]; wc = H4[n2 * 8 + c];
            // prefetch indices for e+128
            int e2 = en + 64;
            if (e2 < hi) {
                n0 = __ldg(hidx + e2); n1 = __ldg(hidx + E + e2); n2 = __ldg(hidx + 2 * E + e2);
            }
        }
        // compute with gathers of e
        float xa[8], xb[8], xc[8], xv[8];
        h2x4_to_f8(va, xa); h2x4_to_f8(vb, xb); h2x4_to_f8(vc, xc);
#pragma unroll
        for (int q = 0; q < 8; q++) xv[q] = xa[q] + xb[q] + xc[q];
        uint4 o;
        o.x = pack_h2(xv[0], xv[1]); o.y = pack_h2(xv[2], xv[3]);
        o.z = pack_h2(xv[4], xv[5]); o.w = pack_h2(xv[6], xv[7]);
        XH4[(size_t)e * 8 + c] = o;
#pragma unroll
        for (int q = 0; q < 8; q++) {
            float xq = xv[q];
            if (xq > m[q]) { s[q] = s[q] * __expf(m[q] - xq) + 1.f; m[q] = xq; }
            else           { s[q] += __expf(xq - m[q]); }
        }
        e = en;
        if (e < hi) { va = wa; vb = wb2; vc = wc; }
    }

    if (writeBatch) {
        float gf = (float)g;
        for (int ee = lo + tid; ee < hi; ee += 512) out[E + ee] = gf;
    }

    int slot = w * 4 + j;     // 0..63
    *(float4*)&sm_m[slot][c * 8]     = make_float4(m[0], m[1], m[2], m[3]);
    *(float4*)&sm_m[slot][c * 8 + 4] = make_float4(m[4], m[5], m[6], m[7]);
    *(float4*)&sm_s[slot][c * 8]     = make_float4(s[0], s[1], s[2], s[3]);
    *(float4*)&sm_s[slot][c * 8 + 4] = make_float4(s[4], s[5], s[6], s[7]);
    __syncthreads();

    if (tid < 64) {
        int f = tid;
        float M = -3.0e38f;
#pragma unroll 8
        for (int sl = 0; sl < 64; sl++) M = fmaxf(M, sm_m[sl][f]);
        float S = 0.f;
#pragma unroll 8
        for (int sl = 0; sl < 64; sl++) {
            float mv = sm_m[sl][f];
            if (mv > -1.0e38f) S += sm_s[sl][f] * __expf(mv - M);
        }
        float R = (S > 0.f) ? (1.f / S) : 0.f;
        g_segmr[g * 64 + f] = make_float2(M, R);
    }
}

// ---------------------------------------------------------------------------
// K3: fp16 tensor-core main kernel with software-pipelined staging:
// xh data AND softmax stats for the next tile are loaded during the GEMM
// phase of the current tile.
// ---------------------------------------------------------------------------
#define OFF_WT  0
#define OFF_V1  8192
#define OFF_V2  24576
#define OFF_C1  32768
#define OFF_C2  33024
#define OFF_V3  33280
#define OFF_C3  33536
#define OFF_WRP 33792
#define WRP_SZ  4096
#define SMEM_MAIN (OFF_WRP + 8 * WRP_SZ)   // 66560

__global__ __launch_bounds__(256, 2)
void k_main_mma(const int* __restrict__ bh,
                const float* __restrict__ Wt,
                const float* __restrict__ V1, const float* __restrict__ c1,
                const float* __restrict__ V2, const float* __restrict__ c2,
                const float* __restrict__ V3, const float* __restrict__ c3,
                float* __restrict__ out, int E)
{
    extern __shared__ __align__(128) char smem[];
    uint32_t sb = smem_u32(smem);
    int tid = threadIdx.x;

    // ---- stage weights as [n][k] fp16, xor-swizzled per row ----
    for (int i = tid; i < 64 * 64; i += 256) {
        int n = i >> 6, k = i & 63;
        uint32_t off = (uint32_t)n * 128 + (((uint32_t)k * 2) ^ (((uint32_t)n & 7) * 16));
        *(__half*)(smem + OFF_WT + off) = __float2half(Wt[k * 64 + n]);
        *(__half*)(smem + OFF_V2 + off) = __float2half(V2[k * 64 + n]);
    }
    for (int i = tid; i < 64 * 128; i += 256) {
        int n = i >> 7, k = i & 127;
        uint32_t off = (uint32_t)n * 256 + (((uint32_t)k * 2) ^ (((uint32_t)n & 7) * 16));
        *(__half*)(smem + OFF_V1 + off) = __float2half(V1[k * 64 + n]);
    }
    for (int i = tid; i < 64; i += 256) {
        ((float*)(smem + OFF_C1))[i] = c1[i];
        ((float*)(smem + OFF_C2))[i] = c2[i];
        ((float*)(smem + OFF_V3))[i] = V3[i];
    }
    if (tid == 0) *(float*)(smem + OFF_C3) = c3[0];
    __syncthreads();

    const float* sc1 = (const float*)(smem + OFF_C1);
    const float* sc2 = (const float*)(smem + OFF_C2);
    const float* sV3 = (const float*)(smem + OFF_V3);
    const float  c3v = *(const float*)(smem + OFF_C3);

    int warp = tid >> 5, lane = tid & 31;
    char* wbase = smem + OFF_WRP + warp * WRP_SZ;
    char* sxh  = wbase;          // 16 x 128B
    char* scf  = wbase + 2048;
    uint32_t sxh_u = sb + OFF_WRP + warp * WRP_SZ;

    // per-lane ldmatrix address components
    int rowA = lane & 15;
    uint32_t aOff = (uint32_t)rowA * 128;
    uint32_t aKx  = ((uint32_t)(lane >> 4)) * 16;
    uint32_t aXor = ((uint32_t)(rowA & 7)) * 16;

    int rowB = (lane & 7) + ((lane >> 4) & 1) * 8;
    uint32_t bKx  = ((uint32_t)((lane >> 3) & 1)) * 16;
    uint32_t bXor = ((uint32_t)(lane & 7)) * 16;

    int qr = lane >> 2;
    int qc = lane & 3;
    uint32_t qxor = (uint32_t)qr * 16;

    // wide-staging lane mapping
    int sc_ = lane & 7;             // 16B chunk (features sc_*8..sc_*8+7)
    int srow = lane >> 3;           // row offset within 4-row pass

    int ngrp = (E + 15) >> 4;
    int gwid = blockIdx.x * 8 + warp;
    int nwrp = gridDim.x * 8;

    // prefetch state for the upcoming tile
    uint4 pv0, pv1, pv2, pv3;
    float4 ps01, ps23, ps45, ps67;
    int pg0 = 0, pglast = 0;

    // prologue prefetch
    if (gwid < ngrp) {
        int e0 = gwid << 4;
        const uint4* xin4 = (const uint4*)(g_xh + (size_t)e0 * 64);
        int r0 = srow, r1 = 4 + srow, r2 = 8 + srow, r3 = 12 + srow;
        pv0 = (e0 + r0 < E) ? xin4[r0 * 8 + sc_] : make_uint4(0, 0, 0, 0);
        pv1 = (e0 + r1 < E) ? xin4[r1 * 8 + sc_] : make_uint4(0, 0, 0, 0);
        pv2 = (e0 + r2 < E) ? xin4[r2 * 8 + sc_] : make_uint4(0, 0, 0, 0);
        pv3 = (e0 + r3 < E) ? xin4[r3 * 8 + sc_] : make_uint4(0, 0, 0, 0);
        pg0 = __ldg(bh + e0);
        pglast = __ldg(bh + min(e0 + 15, E - 1));
        if (pg0 == pglast) {
            const float4* st = (const float4*)(g_segmr + (size_t)pg0 * 64 + sc_ * 8);
            ps01 = st[0]; ps23 = st[1]; ps45 = st[2]; ps67 = st[3];
        }
    }

    for (int grp = gwid; grp < ngrp; grp += nwrp) {
        int e0 = grp << 4;
        __syncwarp();

        // ---- stage from prefetched registers ----
        if (pg0 == pglast) {
            // fast path: whole tile one graph — stats already prefetched
            uint4 vv[4] = { pv0, pv1, pv2, pv3 };
#pragma unroll
            for (int p = 0; p < 4; p++) {
                int row = p * 4 + srow;
                float xv[8];
                h2x4_to_f8(vv[p], xv);
                uint4 cfv;
                cfv.x = pack_h2(__expf(xv[0] - ps01.x) * ps01.y, __expf(xv[1] - ps01.z) * ps01.w);
                cfv.y = pack_h2(__expf(xv[2] - ps23.x) * ps23.y, __expf(xv[3] - ps23.z) * ps23.w);
                cfv.z = pack_h2(__expf(xv[4] - ps45.x) * ps45.y, __expf(xv[5] - ps45.z) * ps45.w);
                cfv.w = pack_h2(__expf(xv[6] - ps67.x) * ps67.y, __expf(xv[7] - ps67.z) * ps67.w);
                uint32_t off = (uint32_t)row * 128 +
                               (((uint32_t)sc_ * 16) ^ (((uint32_t)(row & 7)) * 16));
                *(uint4*)(sxh + off) = vv[p];
                *(uint4*)(scf + off) = cfv;
            }
        } else {
            // slow path: write xh tiles first, then per-edge cf from smem
            uint4 vv[4] = { pv0, pv1, pv2, pv3 };
#pragma unroll
            for (int p = 0; p < 4; p++) {
                int row = p * 4 + srow;
                uint32_t off = (uint32_t)row * 128 +
                               (((uint32_t)sc_ * 16) ^ (((uint32_t)(row & 7)) * 16));
                *(uint4*)(sxh + off) = vv[p];
            }
            __syncwarp();
#pragma unroll 4
            for (int it = 0; it < 16; it++) {
                int e = e0 + it;
                uint32_t off = (uint32_t)it * 128 + (((uint32_t)lane * 4) ^ (((uint32_t)it & 7) * 16));
                if (e < E) {
                    int g = __ldg(bh + e);
                    __half2 xh2 = *(__half2*)(sxh + off);
                    float2 xv = __half22float2(xh2);
                    float4 mr = *(const float4*)(g_segmr + (size_t)g * 64 + 2 * lane);
                    float cfa = __expf(xv.x - mr.x) * mr.y;
                    float cfb = __expf(xv.y - mr.z) * mr.w;
                    *(__half2*)(scf + off) = __floats2half2_rn(cfa, cfb);
                } else {
                    *(__half2*)(scf + off) = __floats2half2_rn(0.f, 0.f);
                }
            }
        }
        __syncwarp();

        // ---- issue prefetch for next tile (hidden under the GEMM phase) ----
        int nxt = grp + nwrp;
        if (nxt < ngrp) {
            int ne0 = nxt << 4;
            const uint4* xin4 = (const uint4*)(g_xh + (size_t)ne0 * 64);
            int r0 = srow, r1 = 4 + srow, r2 = 8 + srow, r3 = 12 + srow;
            pv0 = (ne0 + r0 < E) ? xin4[r0 * 8 + sc_] : make_uint4(0, 0, 0, 0);
            pv1 = (ne0 + r1 < E) ? xin4[r1 * 8 + sc_] : make_uint4(0, 0, 0, 0);
            pv2 = (ne0 + r2 < E) ? xin4[r2 * 8 + sc_] : make_uint4(0, 0, 0, 0);
            pv3 = (ne0 + r3 < E) ? xin4[r3 * 8 + sc_] : make_uint4(0, 0, 0, 0);
            pg0 = __ldg(bh + ne0);
            pglast = __ldg(bh + min(ne0 + 15, E - 1));
            if (pg0 == pglast) {
                const float4* st = (const float4*)(g_segmr + (size_t)pg0 * 64 + sc_ * 8);
                ps01 = st[0]; ps23 = st[1]; ps45 = st[2]; ps67 = st[3];
            }
        }

        float d[8][4];
        uint32_t axh[4][4];    // A-frags of xh (k 0..63), reused by GEMM1+GEMM2
        uint32_t ax2[4][4];    // A-frags of xhh (GEMM2 k 64..127), then o1 (GEMM3)

        // ================= GEMM1: D = xh @ weight =================
#pragma unroll
        for (int j = 0; j < 8; j++) { d[j][0] = 0.f; d[j][1] = 0.f; d[j][2] = 0.f; d[j][3] = 0.f; }
#pragma unroll
        for (int kt = 0; kt < 4; kt++) {
            ldsm4(axh[kt][0], axh[kt][1], axh[kt][2], axh[kt][3],
                  sxh_u + aOff + (((uint32_t)kt * 32 + aKx) ^ aXor));
#pragma unroll
            for (int jt = 0; jt < 4; jt++) {
                uint32_t b0, b1, b2, b3;
                uint32_t baddr = sb + OFF_WT + (uint32_t)(jt * 16 + rowB) * 128
                               + (((uint32_t)kt * 32 + bKx) ^ bXor);
                ldsm4(b0, b1, b2, b3, baddr);
                mma_f16(d[2 * jt],     axh[kt][0], axh[kt][1], axh[kt][2], axh[kt][3], b0, b1);
                mma_f16(d[2 * jt + 1], axh[kt][0], axh[kt][1], axh[kt][2], axh[kt][3], b2, b3);
            }
        }
        // epi1 (in registers): xhh = cf * relu(D) -> A-frags for GEMM2 k 64..127
#pragma unroll
        for (int kt = 0; kt < 4; kt++) {
            int j0 = 2 * kt, j1 = j0 + 1;
            uint32_t o00 = (uint32_t)qr * 128 + (((uint32_t)(j0 * 16 + qc * 4)) ^ qxor);
            uint32_t o10 = (uint32_t)qr * 128 + (((uint32_t)(j1 * 16 + qc * 4)) ^ qxor);
            float2 cfa = __half22float2(*(__half2*)(scf + o00));
            float2 cfb = __half22float2(*(__half2*)(scf + o00 + 1024));
            float2 cfc = __half22float2(*(__half2*)(scf + o10));
            float2 cfd = __half22float2(*(__half2*)(scf + o10 + 1024));
            ax2[kt][0] = pack_h2(fmaxf(d[j0][0], 0.f) * cfa.x, fmaxf(d[j0][1], 0.f) * cfa.y);
            ax2[kt][1] = pack_h2(fmaxf(d[j0][2], 0.f) * cfb.x, fmaxf(d[j0][3], 0.f) * cfb.y);
            ax2[kt][2] = pack_h2(fmaxf(d[j1][0], 0.f) * cfc.x, fmaxf(d[j1][1], 0.f) * cfc.y);
            ax2[kt][3] = pack_h2(fmaxf(d[j1][2], 0.f) * cfd.x, fmaxf(d[j1][3], 0.f) * cfd.y);
        }

        // ================= GEMM2: D = [xh | xhh] @ V1 =================
#pragma unroll
        for (int j = 0; j < 8; j++) { d[j][0] = 0.f; d[j][1] = 0.f; d[j][2] = 0.f; d[j][3] = 0.f; }
#pragma unroll
        for (int kt = 0; kt < 8; kt++) {
            const uint32_t* a = (kt < 4) ? axh[kt] : ax2[kt - 4];
#pragma unroll
            for (int jt = 0; jt < 4; jt++) {
                uint32_t b0, b1, b2, b3;
                uint32_t baddr = sb + OFF_V1 + (uint32_t)(jt * 16 + rowB) * 256
                               + (((uint32_t)kt * 32 + bKx) ^ bXor);
                ldsm4(b0, b1, b2, b3, baddr);
                mma_f16(d[2 * jt],     a[0], a[1], a[2], a[3], b0, b1);
                mma_f16(d[2 * jt + 1], a[0], a[1], a[2], a[3], b2, b3);
            }
        }
        // epi2 (in registers): o1 = relu(D + c1) -> A-frags for GEMM3
#pragma unroll
        for (int kt = 0; kt < 4; kt++) {
            int j0 = 2 * kt, j1 = j0 + 1;
            float2 bv0 = *(const float2*)(sc1 + j0 * 8 + qc * 2);
            float2 bv1 = *(const float2*)(sc1 + j1 * 8 + qc * 2);
            ax2[kt][0] = pack_h2(fmaxf(d[j0][0] + bv0.x, 0.f), fmaxf(d[j0][1] + bv0.y, 0.f));
            ax2[kt][1] = pack_h2(fmaxf(d[j0][2] + bv0.x, 0.f), fmaxf(d[j0][3] + bv0.y, 0.f));
            ax2[kt][2] = pack_h2(fmaxf(d[j1][0] + bv1.x, 0.f), fmaxf(d[j1][1] + bv1.y, 0.f));
            ax2[kt][3] = pack_h2(fmaxf(d[j1][2] + bv1.x, 0.f), fmaxf(d[j1][3] + bv1.y, 0.f));
        }

        // ================= GEMM3: D = o1 @ V2 =================
#pragma unroll
        for (int j = 0; j < 8; j++) { d[j][0] = 0.f; d[j][1] = 0.f; d[j][2] = 0.f; d[j][3] = 0.f; }
#pragma unroll
        for (int kt = 0; kt < 4; kt++) {
#pragma unroll
            for (int jt = 0; jt < 4; jt++) {
                uint32_t b0, b1, b2, b3;
                uint32_t baddr = sb + OFF_V2 + (uint32_t)(jt * 16 + rowB) * 128
                               + (((uint32_t)kt * 32 + bKx) ^ bXor);
                ldsm4(b0, b1, b2, b3, baddr);
                mma_f16(d[2 * jt],     ax2[kt][0], ax2[kt][1], ax2[kt][2], ax2[kt][3], b0, b1);
                mma_f16(d[2 * jt + 1], ax2[kt][0], ax2[kt][1], ax2[kt][2], ax2[kt][3], b2, b3);
            }
        }
        // epi3: o2 = relu(D + c2); z = o2 . V3 + c3; out = sigmoid(z)
        float zlo = 0.f, zhi = 0.f;
#pragma unroll
        for (int j = 0; j < 8; j++) {
            int col = j * 8 + qc * 2;
            float2 bv = *(const float2*)(sc2 + col);
            float2 wv = *(const float2*)(sV3 + col);
            zlo = fmaf(fmaxf(d[j][0] + bv.x, 0.f), wv.x, zlo);
            zlo = fmaf(fmaxf(d[j][1] + bv.y, 0.f), wv.y, zlo);
            zhi = fmaf(fmaxf(d[j][2] + bv.x, 0.f), wv.x, zhi);
            zhi = fmaf(fmaxf(d[j][3] + bv.y, 0.f), wv.y, zhi);
        }
        zlo += __shfl_xor_sync(0xffffffffu, zlo, 1);
        zlo += __shfl_xor_sync(0xffffffffu, zlo, 2);
        zhi += __shfl_xor_sync(0xffffffffu, zhi, 1);
        zhi += __shfl_xor_sync(0xffffffffu, zhi, 2);
        if (qc == 0) {
            int ea = e0 + qr, eb = e0 + qr + 8;
            if (ea < E) out[ea] = 1.f / (1.f + __expf(-(zlo + c3v)));
            if (eb < E) out[eb] = 1.f / (1.f + __expf(-(zhi + c3v)));
        }
    }
}

// ---------------------------------------------------------------------------
// kernel_launch
// ---------------------------------------------------------------------------
extern "C" void kernel_launch(void* const* d_in, const int* in_sizes, int n_in,
                              void* d_out, int out_size)
{
    const float* x     = (const float*)d_in[0];
    const float* u     = (const float*)d_in[1];
    const int*   batch = (const int*)d_in[2];
    const int*   hidx  = (const int*)d_in[3];
    const int*   bh    = (const int*)d_in[4];

    int N = in_sizes[0] / 6;
    int G = in_sizes[1] / 4;
    int E = in_sizes[4];

    int wb = (in_sizes[5] == 1) ? 6 : 5;   // skip scalar "r" if present
    const float* W1 = (const float*)d_in[wb + 0];
    const float* b1 = (const float*)d_in[wb + 1];
    const float* W2 = (const float*)d_in[wb + 2];
    const float* b2 = (const float*)d_in[wb + 3];
    const float* W3 = (const float*)d_in[wb + 4];
    const float* b3 = (const float*)d_in[wb + 5];
    const float* Wt = (const float*)d_in[wb + 6];
    const float* V1 = (const float*)d_in[wb + 7];
    const float* c1 = (const float*)d_in[wb + 8];
    const float* V2 = (const float*)d_in[wb + 9];
    const float* c2 = (const float*)d_in[wb + 10];
    const float* V3 = (const float*)d_in[wb + 11];
    const float* c3 = (const float*)d_in[wb + 12];

    int writeBatch = (out_size >= 2 * E) ? 1 : 0;

    cudaFuncSetAttribute(k_node_mlp_mma, cudaFuncAttributeMaxDynamicSharedMemorySize, K1_SMEM);
    k_node_mlp_mma<<<(N + 127) / 128, 256, K1_SMEM>>>(x, u, batch, W1, b1, W2, b2, W3, b3, N);

    k_segstats<<<G, 512>>>(hidx, bh, E, (float*)d_out, writeBatch);

    int nsm = 148;
    cudaDeviceGetAttribute(&nsm, cudaDevAttrMultiProcessorCount, 0);
    cudaFuncSetAttribute(k_main_mma, cudaFuncAttributeMaxDynamicSharedMemorySize, SMEM_MAIN);
    k_main_mma<<<nsm * 2, 256, SMEM_MAIN>>>(bh, Wt, V1, c1, V2, c2, V3, c3,
                                            (float*)d_out, E);
}

// round 13
// speedup vs baseline: 1.0514x; 1.0514x over previous
#include <cuda_runtime.h>
#include <cuda_fp16.h>
#include <cstdint>
#include <math.h>

// Problem constants (fixed shapes for this registry entry)
#define NMAX 32768
#define GMAX 2048
#define EMAX 1146880

// Scratch (no cudaMalloc allowed)
__device__ __half  g_h[NMAX * 64];         // node embeddings fp16 [N,64] (4 MB)
__device__ float2  g_segmr[GMAX * 64];     // per-graph per-feature (max, 1/sum)
__device__ __half  g_xh[(size_t)EMAX * 64];// hyperedge features, fp16 (147 MB)

// ---------------------------------------------------------------------------
// PTX wrappers (portable tensor path: ldmatrix + mma.sync, compute_103-safe)
// ---------------------------------------------------------------------------
__device__ __forceinline__ uint32_t smem_u32(const void* p) {
    uint32_t a;
    asm("{ .reg .u64 t; cvta.to.shared.u64 t, %1; cvt.u32.u64 %0, t; }" : "=r"(a) : "l"(p));
    return a;
}
__device__ __forceinline__ void ldsm4(uint32_t& r0, uint32_t& r1, uint32_t& r2, uint32_t& r3,
                                      uint32_t addr) {
    asm volatile("ldmatrix.sync.aligned.m8n8.x4.shared.b16 {%0,%1,%2,%3}, [%4];"
                 : "=r"(r0), "=r"(r1), "=r"(r2), "=r"(r3) : "r"(addr));
}
__device__ __forceinline__ void mma_f16(float d[4], uint32_t a0, uint32_t a1, uint32_t a2,
                                        uint32_t a3, uint32_t b0, uint32_t b1) {
    asm volatile(
        "mma.sync.aligned.m16n8k16.row.col.f32.f16.f16.f32 "
        "{%0,%1,%2,%3},{%4,%5,%6,%7},{%8,%9},{%0,%1,%2,%3};"
        : "+f"(d[0]), "+f"(d[1]), "+f"(d[2]), "+f"(d[3])
        : "r"(a0), "r"(a1), "r"(a2), "r"(a3), "r"(b0), "r"(b1));
}
__device__ __forceinline__ uint32_t pack_h2(float lo, float hi) {
    uint32_t r;
    asm("cvt.rn.f16x2.f32 %0, %1, %2;" : "=r"(r) : "f"(hi), "f"(lo));
    return r;
}
__device__ __forceinline__ void h2x4_to_f8(uint4 v, float* x) {
    float2 t;
    t = __half22float2(*(__half2*)&v.x); x[0] = t.x; x[1] = t.y;
    t = __half22float2(*(__half2*)&v.y); x[2] = t.x; x[3] = t.y;
    t = __half22float2(*(__half2*)&v.z); x[4] = t.x; x[5] = t.y;
    t = __half22float2(*(__half2*)&v.w); x[6] = t.x; x[7] = t.y;
}

// ---------------------------------------------------------------------------
// K1: node MLP via fp16 MMA (unchanged from R10/R11).
// ---------------------------------------------------------------------------
#define K1_W1   0
#define K1_W2   8192
#define K1_W3   16384
#define K1_B1   24576
#define K1_B2   24832
#define K1_B3   25088
#define K1_IN   25344
#define K1_SMEM (K1_IN + 8 * 2048)   // 41728

__global__ __launch_bounds__(256)
void k_node_mlp_mma(const float* __restrict__ x, const float* __restrict__ u,
                    const int* __restrict__ batch,
                    const float* __restrict__ W1, const float* __restrict__ b1,
                    const float* __restrict__ W2, const float* __restrict__ b2,
                    const float* __restrict__ W3, const float* __restrict__ b3,
                    int n)
{
    extern __shared__ __align__(128) char smem[];
    uint32_t sb = smem_u32(smem);
    int tid = threadIdx.x;

    for (int i = tid; i < 64 * 16; i += 256) {
        int nn = i >> 4, k = i & 15;
        uint32_t off = (uint32_t)nn * 128 + (((uint32_t)k * 2) ^ (((uint32_t)nn & 7) * 16));
        *(__half*)(smem + K1_W1 + off) = __float2half(W1[k * 64 + nn]);
    }
    for (int i = tid; i < 64 * 64; i += 256) {
        int nn = i >> 6, k = i & 63;
        uint32_t off = (uint32_t)nn * 128 + (((uint32_t)k * 2) ^ (((uint32_t)nn & 7) * 16));
        *(__half*)(smem + K1_W2 + off) = __float2half(W2[k * 64 + nn]);
        *(__half*)(smem + K1_W3 + off) = __float2half(W3[k * 64 + nn]);
    }
    for (int i = tid; i < 64; i += 256) {
        ((float*)(smem + K1_B1))[i] = b1[i];
        ((float*)(smem + K1_B2))[i] = b2[i];
        ((float*)(smem + K1_B3))[i] = b3[i];
    }
    __syncthreads();

    const float* sB1 = (const float*)(smem + K1_B1);
    const float* sB2 = (const float*)(smem + K1_B2);
    const float* sB3 = (const float*)(smem + K1_B3);

    int warp = tid >> 5, lane = tid & 31;
    char* sin = smem + K1_IN + warp * 2048;
    uint32_t sin_u = sb + K1_IN + (uint32_t)warp * 2048;

    int node0 = (blockIdx.x * 8 + warp) * 16;

    {
        int r = lane >> 1;
        int halfc = lane & 1;
        int nd = node0 + r;
        uint32_t off = (uint32_t)r * 128 + (((uint32_t)halfc * 16) ^ (((uint32_t)(r & 7)) * 16));
        uint4 v = make_uint4(0, 0, 0, 0);
        if (nd < n) {
            int b = __ldg(batch + nd);
            if (halfc == 0) {
                float2 a0 = *(const float2*)(x + (size_t)nd * 6);
                float2 a1 = *(const float2*)(x + (size_t)nd * 6 + 2);
                float2 a2 = *(const float2*)(x + (size_t)nd * 6 + 4);
                float2 u0 = *(const float2*)(u + (size_t)b * 4);
                v.x = pack_h2(a0.x, a0.y);
                v.y = pack_h2(a1.x, a1.y);
                v.z = pack_h2(a2.x, a2.y);
                v.w = pack_h2(u0.x, u0.y);
            } else {
                float2 u1 = *(const float2*)(u + (size_t)b * 4 + 2);
                v.x = pack_h2(u1.x, u1.y);
            }
        }
        *(uint4*)(sin + off) = v;
    }
    __syncwarp();

    int rowA = lane & 15;
    uint32_t aKx  = ((uint32_t)(lane >> 4)) * 16;
    uint32_t aXor = ((uint32_t)(rowA & 7)) * 16;
    int rowB = (lane & 7) + ((lane >> 4) & 1) * 8;
    uint32_t bKx  = ((uint32_t)((lane >> 3) & 1)) * 16;
    uint32_t bXor = ((uint32_t)(lane & 7)) * 16;
    int qr = lane >> 2;
    int qc = lane & 3;

    float d[8][4];
    uint32_t ax[4][4];

#pragma unroll
    for (int j = 0; j < 8; j++) { d[j][0] = 0.f; d[j][1] = 0.f; d[j][2] = 0.f; d[j][3] = 0.f; }
    {
        uint32_t a0, a1, a2, a3;
        ldsm4(a0, a1, a2, a3, sin_u + (uint32_t)rowA * 128 + (aKx ^ aXor));
#pragma unroll
        for (int jt = 0; jt < 4; jt++) {
            uint32_t b0, b1r, b2r, b3r;
            uint32_t baddr = sb + K1_W1 + (uint32_t)(jt * 16 + rowB) * 128 + (bKx ^ bXor);
            ldsm4(b0, b1r, b2r, b3r, baddr);
            mma_f16(d[2 * jt],     a0, a1, a2, a3, b0, b1r);
            mma_f16(d[2 * jt + 1], a0, a1, a2, a3, b2r, b3r);
        }
    }
#pragma unroll
    for (int kt = 0; kt < 4; kt++) {
        int j0 = 2 * kt, j1 = j0 + 1;
        float2 bv0 = *(const float2*)(sB1 + j0 * 8 + qc * 2);
        float2 bv1 = *(const float2*)(sB1 + j1 * 8 + qc * 2);
        ax[kt][0] = pack_h2(fmaxf(d[j0][0] + bv0.x, 0.f), fmaxf(d[j0][1] + bv0.y, 0.f));
        ax[kt][1] = pack_h2(fmaxf(d[j0][2] + bv0.x, 0.f), fmaxf(d[j0][3] + bv0.y, 0.f));
        ax[kt][2] = pack_h2(fmaxf(d[j1][0] + bv1.x, 0.f), fmaxf(d[j1][1] + bv1.y, 0.f));
        ax[kt][3] = pack_h2(fmaxf(d[j1][2] + bv1.x, 0.f), fmaxf(d[j1][3] + bv1.y, 0.f));
    }

#pragma unroll
    for (int j = 0; j < 8; j++) { d[j][0] = 0.f; d[j][1] = 0.f; d[j][2] = 0.f; d[j][3] = 0.f; }
#pragma unroll
    for (int kt = 0; kt < 4; kt++) {
#pragma unroll
        for (int jt = 0; jt < 4; jt++) {
            uint32_t b0, b1r, b2r, b3r;
            uint32_t baddr = sb + K1_W2 + (uint32_t)(jt * 16 + rowB) * 128
                           + (((uint32_t)kt * 32 + bKx) ^ bXor);
            ldsm4(b0, b1r, b2r, b3r, baddr);
            mma_f16(d[2 * jt],     ax[kt][0], ax[kt][1], ax[kt][2], ax[kt][3], b0, b1r);
            mma_f16(d[2 * jt + 1], ax[kt][0], ax[kt][1], ax[kt][2], ax[kt][3], b2r, b3r);
        }
    }
#pragma unroll
    for (int kt = 0; kt < 4; kt++) {
        int j0 = 2 * kt, j1 = j0 + 1;
        float2 bv0 = *(const float2*)(sB2 + j0 * 8 + qc * 2);
        float2 bv1 = *(const float2*)(sB2 + j1 * 8 + qc * 2);
        ax[kt][0] = pack_h2(fmaxf(d[j0][0] + bv0.x, 0.f), fmaxf(d[j0][1] + bv0.y, 0.f));
        ax[kt][1] = pack_h2(fmaxf(d[j0][2] + bv0.x, 0.f), fmaxf(d[j0][3] + bv0.y, 0.f));
        ax[kt][2] = pack_h2(fmaxf(d[j1][0] + bv1.x, 0.f), fmaxf(d[j1][1] + bv1.y, 0.f));
        ax[kt][3] = pack_h2(fmaxf(d[j1][2] + bv1.x, 0.f), fmaxf(d[j1][3] + bv1.y, 0.f));
    }

#pragma unroll
    for (int j = 0; j < 8; j++) { d[j][0] = 0.f; d[j][1] = 0.f; d[j][2] = 0.f; d[j][3] = 0.f; }
#pragma unroll
    for (int kt = 0; kt < 4; kt++) {
#pragma unroll
        for (int jt = 0; jt < 4; jt++) {
            uint32_t b0, b1r, b2r, b3r;
            uint32_t baddr = sb + K1_W3 + (uint32_t)(jt * 16 + rowB) * 128
                           + (((uint32_t)kt * 32 + bKx) ^ bXor);
            ldsm4(b0, b1r, b2r, b3r, baddr);
            mma_f16(d[2 * jt],     ax[kt][0], ax[kt][1], ax[kt][2], ax[kt][3], b0, b1r);
            mma_f16(d[2 * jt + 1], ax[kt][0], ax[kt][1], ax[kt][2], ax[kt][3], b2r, b3r);
        }
    }
    {
        __half2* Gh2 = (__half2*)g_h;
        int na = node0 + qr, nb = node0 + qr + 8;
#pragma unroll
        for (int j = 0; j < 8; j++) {
            float2 bv = *(const float2*)(sB3 + j * 8 + qc * 2);
            int fp = j * 4 + qc;
            if (na < n)
                Gh2[(size_t)na * 32 + fp] = __floats2half2_rn(d[j][0] + bv.x, d[j][1] + bv.y);
            if (nb < n)
                Gh2[(size_t)nb * 32 + fp] = __floats2half2_rn(d[j][2] + bv.x, d[j][3] + bv.y);
        }
    }
}

// ---------------------------------------------------------------------------
// K2: segment softmax stats + x_hyper materialization, 2-deep pipelined:
// indices prefetched 1 iter ahead of their gathers; gathers issued 1 iter
// ahead of their compute. (Isolated change vs R11.)
// ---------------------------------------------------------------------------
__device__ __forceinline__ int lbound(const int* __restrict__ a, int n, int key)
{
    int lo = 0, hi = n;
    while (lo < hi) { int mid = (lo + hi) >> 1; if (a[mid] < key) lo = mid + 1; else hi = mid; }
    return lo;
}

__global__ __launch_bounds__(512)
void k_segstats(const int* __restrict__ hidx, const int* __restrict__ bh, int E,
                float* __restrict__ out, int writeBatch)
{
    __shared__ float sm_m[64][64];
    __shared__ float sm_s[64][64];

    int g = blockIdx.x;
    int lo = lbound(bh, E, g);
    int hi = lbound(bh, E, g + 1);

    int tid = threadIdx.x;
    int w = tid >> 5, lane = tid & 31;
    int j = lane >> 3;       // edge slot within warp (0..3)
    int c = lane & 7;        // 16B chunk (features c*8 .. c*8+7)

    const uint4* H4 = (const uint4*)g_h;
    uint4* XH4 = (uint4*)g_xh;

    float m[8], s[8];
#pragma unroll
    for (int q = 0; q < 8; q++) { m[q] = -3.0e38f; s[q] = 0.f; }

    int e = lo + w * 4 + j;

    // pipeline state: gathers for edge e in registers; indices for e+64
    uint4 va = make_uint4(0,0,0,0), vb = va, vc = va;
    int n0 = 0, n1 = 0, n2 = 0;
    if (e < hi) {
        int i0 = __ldg(hidx + e), i1 = __ldg(hidx + E + e), i2 = __ldg(hidx + 2 * E + e);
        va = H4[i0 * 8 + c]; vb = H4[i1 * 8 + c]; vc = H4[i2 * 8 + c];
        int en = e + 64;
        if (en < hi) {
            n0 = __ldg(hidx + en); n1 = __ldg(hidx + E + en); n2 = __ldg(hidx + 2 * E + en);
        }
    }

    while (e < hi) {
        int en = e + 64;
        // issue gathers for e+64 (indices prefetched last iteration)
        uint4 wa, wb2, wc;
        if (en < hi) {
            wa = H4[n0 * 8 + c]; wb2 = H4[n1 * 8 + c]; wc = H4[n2 * 8 + c];
            int e2 = en + 64;
            if (e2 < hi) {
                n0 = __ldg(hidx + e2); n1 = __ldg(hidx + E + e2); n2 = __ldg(hidx + 2 * E + e2);
            }
        }
        // compute with gathers of e
        float xa[8], xb[8], xc[8], xv[8];
        h2x4_to_f8(va, xa); h2x4_to_f8(vb, xb); h2x4_to_f8(vc, xc);
#pragma unroll
        for (int q = 0; q < 8; q++) xv[q] = xa[q] + xb[q] + xc[q];
        uint4 o;
        o.x = pack_h2(xv[0], xv[1]); o.y = pack_h2(xv[2], xv[3]);
        o.z = pack_h2(xv[4], xv[5]); o.w = pack_h2(xv[6], xv[7]);
        XH4[(size_t)e * 8 + c] = o;
#pragma unroll
        for (int q = 0; q < 8; q++) {
            float xq = xv[q];
            if (xq > m[q]) { s[q] = s[q] * __expf(m[q] - xq) + 1.f; m[q] = xq; }
            else           { s[q] += __expf(xq - m[q]); }
        }
        e = en;
        if (e < hi) { va = wa; vb = wb2; vc = wc; }
    }

    if (writeBatch) {
        float gf = (float)g;
        for (int ee = lo + tid; ee < hi; ee += 512) out[E + ee] = gf;
    }

    int slot = w * 4 + j;     // 0..63
    *(float4*)&sm_m[slot][c * 8]     = make_float4(m[0], m[1], m[2], m[3]);
    *(float4*)&sm_m[slot][c * 8 + 4] = make_float4(m[4], m[5], m[6], m[7]);
    *(float4*)&sm_s[slot][c * 8]     = make_float4(s[0], s[1], s[2], s[3]);
    *(float4*)&sm_s[slot][c * 8 + 4] = make_float4(s[4], s[5], s[6], s[7]);
    __syncthreads();

    if (tid < 64) {
        int f = tid;
        float M = -3.0e38f;
#pragma unroll 8
        for (int sl = 0; sl < 64; sl++) M = fmaxf(M, sm_m[sl][f]);
        float S = 0.f;
#pragma unroll 8
        for (int sl = 0; sl < 64; sl++) {
            float mv = sm_m[sl][f];
            if (mv > -1.0e38f) S += sm_s[sl][f] * __expf(mv - M);
        }
        float R = (S > 0.f) ? (1.f / S) : 0.f;
        g_segmr[g * 64 + f] = make_float2(M, R);
    }
}

// ---------------------------------------------------------------------------
// K3: fp16 tensor-core main kernel — EXACT R11 champion version
// (software-pipelined xh staging only; NO stat prefetch).
// ---------------------------------------------------------------------------
#define OFF_WT  0
#define OFF_V1  8192
#define OFF_V2  24576
#define OFF_C1  32768
#define OFF_C2  33024
#define OFF_V3  33280
#define OFF_C3  33536
#define OFF_WRP 33792
#define WRP_SZ  4096
#define SMEM_MAIN (OFF_WRP + 8 * WRP_SZ)   // 66560

__global__ __launch_bounds__(256, 2)
void k_main_mma(const int* __restrict__ bh,
                const float* __restrict__ Wt,
                const float* __restrict__ V1, const float* __restrict__ c1,
                const float* __restrict__ V2, const float* __restrict__ c2,
                const float* __restrict__ V3, const float* __restrict__ c3,
                float* __restrict__ out, int E)
{
    extern __shared__ __align__(128) char smem[];
    uint32_t sb = smem_u32(smem);
    int tid = threadIdx.x;

    // ---- stage weights as [n][k] fp16, xor-swizzled per row ----
    for (int i = tid; i < 64 * 64; i += 256) {
        int n = i >> 6, k = i & 63;
        uint32_t off = (uint32_t)n * 128 + (((uint32_t)k * 2) ^ (((uint32_t)n & 7) * 16));
        *(__half*)(smem + OFF_WT + off) = __float2half(Wt[k * 64 + n]);
        *(__half*)(smem + OFF_V2 + off) = __float2half(V2[k * 64 + n]);
    }
    for (int i = tid; i < 64 * 128; i += 256) {
        int n = i >> 7, k = i & 127;
        uint32_t off = (uint32_t)n * 256 + (((uint32_t)k * 2) ^ (((uint32_t)n & 7) * 16));
        *(__half*)(smem + OFF_V1 + off) = __float2half(V1[k * 64 + n]);
    }
    for (int i = tid; i < 64; i += 256) {
        ((float*)(smem + OFF_C1))[i] = c1[i];
        ((float*)(smem + OFF_C2))[i] = c2[i];
        ((float*)(smem + OFF_V3))[i] = V3[i];
    }
    if (tid == 0) *(float*)(smem + OFF_C3) = c3[0];
    __syncthreads();

    const float* sc1 = (const float*)(smem + OFF_C1);
    const float* sc2 = (const float*)(smem + OFF_C2);
    const float* sV3 = (const float*)(smem + OFF_V3);
    const float  c3v = *(const float*)(smem + OFF_C3);

    int warp = tid >> 5, lane = tid & 31;
    char* wbase = smem + OFF_WRP + warp * WRP_SZ;
    char* sxh  = wbase;          // 16 x 128B
    char* scf  = wbase + 2048;
    uint32_t sxh_u = sb + OFF_WRP + warp * WRP_SZ;

    // per-lane ldmatrix address components
    int rowA = lane & 15;
    uint32_t aOff = (uint32_t)rowA * 128;
    uint32_t aKx  = ((uint32_t)(lane >> 4)) * 16;
    uint32_t aXor = ((uint32_t)(rowA & 7)) * 16;

    int rowB = (lane & 7) + ((lane >> 4) & 1) * 8;
    uint32_t bKx  = ((uint32_t)((lane >> 3) & 1)) * 16;
    uint32_t bXor = ((uint32_t)(lane & 7)) * 16;

    int qr = lane >> 2;
    int qc = lane & 3;
    uint32_t qxor = (uint32_t)qr * 16;

    // wide-staging lane mapping
    int sc_ = lane & 7;             // 16B chunk (features sc_*8..sc_*8+7)
    int srow = lane >> 3;           // row offset within 4-row pass

    int ngrp = (E + 15) >> 4;
    int gwid = blockIdx.x * 8 + warp;
    int nwrp = gridDim.x * 8;

    // prefetch state for the upcoming tile
    uint4 pv0, pv1, pv2, pv3;
    int pg0 = 0, pglast = 0;

    // prologue prefetch
    if (gwid < ngrp) {
        int e0 = gwid << 4;
        const uint4* xin4 = (const uint4*)(g_xh + (size_t)e0 * 64);
        int r0 = srow, r1 = 4 + srow, r2 = 8 + srow, r3 = 12 + srow;
        pv0 = (e0 + r0 < E) ? xin4[r0 * 8 + sc_] : make_uint4(0, 0, 0, 0);
        pv1 = (e0 + r1 < E) ? xin4[r1 * 8 + sc_] : make_uint4(0, 0, 0, 0);
        pv2 = (e0 + r2 < E) ? xin4[r2 * 8 + sc_] : make_uint4(0, 0, 0, 0);
        pv3 = (e0 + r3 < E) ? xin4[r3 * 8 + sc_] : make_uint4(0, 0, 0, 0);
        pg0 = __ldg(bh + e0);
        pglast = __ldg(bh + min(e0 + 15, E - 1));
    }

    for (int grp = gwid; grp < ngrp; grp += nwrp) {
        int e0 = grp << 4;
        __syncwarp();

        // ---- stage from prefetched registers ----
        if (pg0 == pglast) {
            // fast path: whole tile one graph — compute cf directly
            const float4* st = (const float4*)(g_segmr + (size_t)pg0 * 64 + sc_ * 8);
            float4 s01 = st[0], s23 = st[1], s45 = st[2], s67 = st[3];
            uint4 vv[4] = { pv0, pv1, pv2, pv3 };
#pragma unroll
            for (int p = 0; p < 4; p++) {
                int row = p * 4 + srow;
                float xv[8];
                h2x4_to_f8(vv[p], xv);
                uint4 cfv;
                cfv.x = pack_h2(__expf(xv[0] - s01.x) * s01.y, __expf(xv[1] - s01.z) * s01.w);
                cfv.y = pack_h2(__expf(xv[2] - s23.x) * s23.y, __expf(xv[3] - s23.z) * s23.w);
                cfv.z = pack_h2(__expf(xv[4] - s45.x) * s45.y, __expf(xv[5] - s45.z) * s45.w);
                cfv.w = pack_h2(__expf(xv[6] - s67.x) * s67.y, __expf(xv[7] - s67.z) * s67.w);
                uint32_t off = (uint32_t)row * 128 +
                               (((uint32_t)sc_ * 16) ^ (((uint32_t)(row & 7)) * 16));
                *(uint4*)(sxh + off) = vv[p];
                *(uint4*)(scf + off) = cfv;
            }
        } else {
            // slow path: write xh tiles first, then per-edge cf from smem
            uint4 vv[4] = { pv0, pv1, pv2, pv3 };
#pragma unroll
            for (int p = 0; p < 4; p++) {
                int row = p * 4 + srow;
                uint32_t off = (uint32_t)row * 128 +
                               (((uint32_t)sc_ * 16) ^ (((uint32_t)(row & 7)) * 16));
                *(uint4*)(sxh + off) = vv[p];
            }
            __syncwarp();
#pragma unroll 4
            for (int it = 0; it < 16; it++) {
                int e = e0 + it;
                uint32_t off = (uint32_t)it * 128 + (((uint32_t)lane * 4) ^ (((uint32_t)it & 7) * 16));
                if (e < E) {
                    int g = __ldg(bh + e);
                    __half2 xh2 = *(__half2*)(sxh + off);
                    float2 xv = __half22float2(xh2);
                    float4 mr = *(const float4*)(g_segmr + (size_t)g * 64 + 2 * lane);
                    float cfa = __expf(xv.x - mr.x) * mr.y;
                    float cfb = __expf(xv.y - mr.z) * mr.w;
                    *(__half2*)(scf + off) = __floats2half2_rn(cfa, cfb);
                } else {
                    *(__half2*)(scf + off) = __floats2half2_rn(0.f, 0.f);
                }
            }
        }
        __syncwarp();

        // ---- issue prefetch for next tile (hidden under the GEMM phase) ----
        int nxt = grp + nwrp;
        if (nxt < ngrp) {
            int ne0 = nxt << 4;
            const uint4* xin4 = (const uint4*)(g_xh + (size_t)ne0 * 64);
            int r0 = srow, r1 = 4 + srow, r2 = 8 + srow, r3 = 12 + srow;
            pv0 = (ne0 + r0 < E) ? xin4[r0 * 8 + sc_] : make_uint4(0, 0, 0, 0);
            pv1 = (ne0 + r1 < E) ? xin4[r1 * 8 + sc_] : make_uint4(0, 0, 0, 0);
            pv2 = (ne0 + r2 < E) ? xin4[r2 * 8 + sc_] : make_uint4(0, 0, 0, 0);
            pv3 = (ne0 + r3 < E) ? xin4[r3 * 8 + sc_] : make_uint4(0, 0, 0, 0);
            pg0 = __ldg(bh + ne0);
            pglast = __ldg(bh + min(ne0 + 15, E - 1));
        }

        float d[8][4];
        uint32_t axh[4][4];    // A-frags of xh (k 0..63), reused by GEMM1+GEMM2
        uint32_t ax2[4][4];    // A-frags of xhh (GEMM2 k 64..127), then o1 (GEMM3)

        // ================= GEMM1: D = xh @ weight =================
#pragma unroll
        for (int j = 0; j < 8; j++) { d[j][0] = 0.f; d[j][1] = 0.f; d[j][2] = 0.f; d[j][3] = 0.f; }
#pragma unroll
        for (int kt = 0; kt < 4; kt++) {
            ldsm4(axh[kt][0], axh[kt][1], axh[kt][2], axh[kt][3],
                  sxh_u + aOff + (((uint32_t)kt * 32 + aKx) ^ aXor));
#pragma unroll
            for (int jt = 0; jt < 4; jt++) {
                uint32_t b0, b1, b2, b3;
                uint32_t baddr = sb + OFF_WT + (uint32_t)(jt * 16 + rowB) * 128
                               + (((uint32_t)kt * 32 + bKx) ^ bXor);
                ldsm4(b0, b1, b2, b3, baddr);
                mma_f16(d[2 * jt],     axh[kt][0], axh[kt][1], axh[kt][2], axh[kt][3], b0, b1);
                mma_f16(d[2 * jt + 1], axh[kt][0], axh[kt][1], axh[kt][2], axh[kt][3], b2, b3);
            }
        }
        // epi1 (in registers): xhh = cf * relu(D) -> A-frags for GEMM2 k 64..127
#pragma unroll
        for (int kt = 0; kt < 4; kt++) {
            int j0 = 2 * kt, j1 = j0 + 1;
            uint32_t o00 = (uint32_t)qr * 128 + (((uint32_t)(j0 * 16 + qc * 4)) ^ qxor);
            uint32_t o10 = (uint32_t)qr * 128 + (((uint32_t)(j1 * 16 + qc * 4)) ^ qxor);
            float2 cfa = __half22float2(*(__half2*)(scf + o00));
            float2 cfb = __half22float2(*(__half2*)(scf + o00 + 1024));
            float2 cfc = __half22float2(*(__half2*)(scf + o10));
            float2 cfd = __half22float2(*(__half2*)(scf + o10 + 1024));
            ax2[kt][0] = pack_h2(fmaxf(d[j0][0], 0.f) * cfa.x, fmaxf(d[j0][1], 0.f) * cfa.y);
            ax2[kt][1] = pack_h2(fmaxf(d[j0][2], 0.f) * cfb.x, fmaxf(d[j0][3], 0.f) * cfb.y);
            ax2[kt][2] = pack_h2(fmaxf(d[j1][0], 0.f) * cfc.x, fmaxf(d[j1][1], 0.f) * cfc.y);
            ax2[kt][3] = pack_h2(fmaxf(d[j1][2], 0.f) * cfd.x, fmaxf(d[j1][3], 0.f) * cfd.y);
        }

        // ================= GEMM2: D = [xh | xhh] @ V1 =================
#pragma unroll
        for (int j = 0; j < 8; j++) { d[j][0] = 0.f; d[j][1] = 0.f; d[j][2] = 0.f; d[j][3] = 0.f; }
#pragma unroll
        for (int kt = 0; kt < 8; kt++) {
            const uint32_t* a = (kt < 4) ? axh[kt] : ax2[kt - 4];
#pragma unroll
            for (int jt = 0; jt < 4; jt++) {
                uint32_t b0, b1, b2, b3;
                uint32_t baddr = sb + OFF_V1 + (uint32_t)(jt * 16 + rowB) * 256
                               + (((uint32_t)kt * 32 + bKx) ^ bXor);
                ldsm4(b0, b1, b2, b3, baddr);
                mma_f16(d[2 * jt],     a[0], a[1], a[2], a[3], b0, b1);
                mma_f16(d[2 * jt + 1], a[0], a[1], a[2], a[3], b2, b3);
            }
        }
        // epi2 (in registers): o1 = relu(D + c1) -> A-frags for GEMM3
#pragma unroll
        for (int kt = 0; kt < 4; kt++) {
            int j0 = 2 * kt, j1 = j0 + 1;
            float2 bv0 = *(const float2*)(sc1 + j0 * 8 + qc * 2);
            float2 bv1 = *(const float2*)(sc1 + j1 * 8 + qc * 2);
            ax2[kt][0] = pack_h2(fmaxf(d[j0][0] + bv0.x, 0.f), fmaxf(d[j0][1] + bv0.y, 0.f));
            ax2[kt][1] = pack_h2(fmaxf(d[j0][2] + bv0.x, 0.f), fmaxf(d[j0][3] + bv0.y, 0.f));
            ax2[kt][2] = pack_h2(fmaxf(d[j1][0] + bv1.x, 0.f), fmaxf(d[j1][1] + bv1.y, 0.f));
            ax2[kt][3] = pack_h2(fmaxf(d[j1][2] + bv1.x, 0.f), fmaxf(d[j1][3] + bv1.y, 0.f));
        }

        // ================= GEMM3: D = o1 @ V2 =================
#pragma unroll
        for (int j = 0; j < 8; j++) { d[j][0] = 0.f; d[j][1] = 0.f; d[j][2] = 0.f; d[j][3] = 0.f; }
#pragma unroll
        for (int kt = 0; kt < 4; kt++) {
#pragma unroll
            for (int jt = 0; jt < 4; jt++) {
                uint32_t b0, b1, b2, b3;
                uint32_t baddr = sb + OFF_V2 + (uint32_t)(jt * 16 + rowB) * 128
                               + (((uint32_t)kt * 32 + bKx) ^ bXor);
                ldsm4(b0, b1, b2, b3, baddr);
                mma_f16(d[2 * jt],     ax2[kt][0], ax2[kt][1], ax2[kt][2], ax2[kt][3], b0, b1);
                mma_f16(d[2 * jt + 1], ax2[kt][0], ax2[kt][1], ax2[kt][2], ax2[kt][3], b2, b3);
            }
        }
        // epi3: o2 = relu(D + c2); z = o2 . V3 + c3; out = sigmoid(z)
        float zlo = 0.f, zhi = 0.f;
#pragma unroll
        for (int j = 0; j < 8; j++) {
            int col = j * 8 + qc * 2;
            float2 bv = *(const float2*)(sc2 + col);
            float2 wv = *(const float2*)(sV3 + col);
            zlo = fmaf(fmaxf(d[j][0] + bv.x, 0.f), wv.x, zlo);
            zlo = fmaf(fmaxf(d[j][1] + bv.y, 0.f), wv.y, zlo);
            zhi = fmaf(fmaxf(d[j][2] + bv.x, 0.f), wv.x, zhi);
            zhi = fmaf(fmaxf(d[j][3] + bv.y, 0.f), wv.y, zhi);
        }
        zlo += __shfl_xor_sync(0xffffffffu, zlo, 1);
        zlo += __shfl_xor_sync(0xffffffffu, zlo, 2);
        zhi += __shfl_xor_sync(0xffffffffu, zhi, 1);
        zhi += __shfl_xor_sync(0xffffffffu, zhi, 2);
        if (qc == 0) {
            int ea = e0 + qr, eb = e0 + qr + 8;
            if (ea < E) out[ea] = 1.f / (1.f + __expf(-(zlo + c3v)));
            if (eb < E) out[eb] = 1.f / (1.f + __expf(-(zhi + c3v)));
        }
    }
}

// ---------------------------------------------------------------------------
// kernel_launch
// ---------------------------------------------------------------------------
extern "C" void kernel_launch(void* const* d_in, const int* in_sizes, int n_in,
                              void* d_out, int out_size)
{
    const float* x     = (const float*)d_in[0];
    const float* u     = (const float*)d_in[1];
    const int*   batch = (const int*)d_in[2];
    const int*   hidx  = (const int*)d_in[3];
    const int*   bh    = (const int*)d_in[4];

    int N = in_sizes[0] / 6;
    int G = in_sizes[1] / 4;
    int E = in_sizes[4];

    int wb = (in_sizes[5] == 1) ? 6 : 5;   // skip scalar "r" if present
    const float* W1 = (const float*)d_in[wb + 0];
    const float* b1 = (const float*)d_in[wb + 1];
    const float* W2 = (const float*)d_in[wb + 2];
    const float* b2 = (const float*)d_in[wb + 3];
    const float* W3 = (const float*)d_in[wb + 4];
    const float* b3 = (const float*)d_in[wb + 5];
    const float* Wt = (const float*)d_in[wb + 6];
    const float* V1 = (const float*)d_in[wb + 7];
    const float* c1 = (const float*)d_in[wb + 8];
    const float* V2 = (const float*)d_in[wb + 9];
    const float* c2 = (const float*)d_in[wb + 10];
    const float* V3 = (const float*)d_in[wb + 11];
    const float* c3 = (const float*)d_in[wb + 12];

    int writeBatch = (out_size >= 2 * E) ? 1 : 0;

    cudaFuncSetAttribute(k_node_mlp_mma, cudaFuncAttributeMaxDynamicSharedMemorySize, K1_SMEM);
    k_node_mlp_mma<<<(N + 127) / 128, 256, K1_SMEM>>>(x, u, batch, W1, b1, W2, b2, W3, b3, N);

    k_segstats<<<G, 512>>>(hidx, bh, E, (float*)d_out, writeBatch);

    int nsm = 148;
    cudaDeviceGetAttribute(&nsm, cudaDevAttrMultiProcessorCount, 0);
    cudaFuncSetAttribute(k_main_mma, cudaFuncAttributeMaxDynamicSharedMemorySize, SMEM_MAIN);
    k_main_mma<<<nsm * 2, 256, SMEM_MAIN>>>(bh, Wt, V1, c1, V2, c2, V3, c3,
                                            (float*)d_out, E);
}

// round 14
// speedup vs baseline: 1.2166x; 1.1571x over previous
#include <cuda_runtime.h>
#include <cuda_fp16.h>
#include <cstdint>
#include <math.h>

// Problem constants (fixed shapes for this registry entry)
#define NMAX 32768
#define GMAX 2048
#define EMAX 1146880

// Scratch (no cudaMalloc allowed)
__device__ __half  g_h[NMAX * 64];         // node embeddings fp16 [N,64] (4 MB)
__device__ float2  g_segmr[GMAX * 64];     // per-graph per-feature (max, 1/sum)
__device__ __half  g_xh[(size_t)EMAX * 64];// hyperedge features, fp16 (147 MB)

// ---------------------------------------------------------------------------
// PTX wrappers (portable tensor path: ldmatrix + mma.sync, compute_103-safe)
// ---------------------------------------------------------------------------
__device__ __forceinline__ uint32_t smem_u32(const void* p) {
    uint32_t a;
    asm("{ .reg .u64 t; cvta.to.shared.u64 t, %1; cvt.u32.u64 %0, t; }" : "=r"(a) : "l"(p));
    return a;
}
__device__ __forceinline__ void ldsm4(uint32_t& r0, uint32_t& r1, uint32_t& r2, uint32_t& r3,
                                      uint32_t addr) {
    asm volatile("ldmatrix.sync.aligned.m8n8.x4.shared.b16 {%0,%1,%2,%3}, [%4];"
                 : "=r"(r0), "=r"(r1), "=r"(r2), "=r"(r3) : "r"(addr));
}
__device__ __forceinline__ void mma_f16(float d[4], uint32_t a0, uint32_t a1, uint32_t a2,
                                        uint32_t a3, uint32_t b0, uint32_t b1) {
    asm volatile(
        "mma.sync.aligned.m16n8k16.row.col.f32.f16.f16.f32 "
        "{%0,%1,%2,%3},{%4,%5,%6,%7},{%8,%9},{%0,%1,%2,%3};"
        : "+f"(d[0]), "+f"(d[1]), "+f"(d[2]), "+f"(d[3])
        : "r"(a0), "r"(a1), "r"(a2), "r"(a3), "r"(b0), "r"(b1));
}
__device__ __forceinline__ uint32_t pack_h2(float lo, float hi) {
    uint32_t r;
    asm("cvt.rn.f16x2.f32 %0, %1, %2;" : "=r"(r) : "f"(hi), "f"(lo));
    return r;
}
__device__ __forceinline__ void h2x4_to_f8(uint4 v, float* x) {
    float2 t;
    t = __half22float2(*(__half2*)&v.x); x[0] = t.x; x[1] = t.y;
    t = __half22float2(*(__half2*)&v.y); x[2] = t.x; x[3] = t.y;
    t = __half22float2(*(__half2*)&v.z); x[4] = t.x; x[5] = t.y;
    t = __half22float2(*(__half2*)&v.w); x[6] = t.x; x[7] = t.y;
}
__device__ __forceinline__ void cp_async16(uint32_t dst_smem, const void* src) {
    asm volatile("cp.async.ca.shared.global [%0], [%1], 16;"
                 :: "r"(dst_smem), "l"(src) : "memory");
}
__device__ __forceinline__ void cp_async_commit() {
    asm volatile("cp.async.commit_group;" ::: "memory");
}
__device__ __forceinline__ void cp_async_wait_all() {
    asm volatile("cp.async.wait_group 0;" ::: "memory");
}

// ---------------------------------------------------------------------------
// K1: node MLP via fp16 MMA (unchanged from R10/R11).
// ---------------------------------------------------------------------------
#define K1_W1   0
#define K1_W2   8192
#define K1_W3   16384
#define K1_B1   24576
#define K1_B2   24832
#define K1_B3   25088
#define K1_IN   25344
#define K1_SMEM (K1_IN + 8 * 2048)   // 41728

__global__ __launch_bounds__(256)
void k_node_mlp_mma(const float* __restrict__ x, const float* __restrict__ u,
                    const int* __restrict__ batch,
                    const float* __restrict__ W1, const float* __restrict__ b1,
                    const float* __restrict__ W2, const float* __restrict__ b2,
                    const float* __restrict__ W3, const float* __restrict__ b3,
                    int n)
{
    extern __shared__ __align__(128) char smem[];
    uint32_t sb = smem_u32(smem);
    int tid = threadIdx.x;

    for (int i = tid; i < 64 * 16; i += 256) {
        int nn = i >> 4, k = i & 15;
        uint32_t off = (uint32_t)nn * 128 + (((uint32_t)k * 2) ^ (((uint32_t)nn & 7) * 16));
        *(__half*)(smem + K1_W1 + off) = __float2half(W1[k * 64 + nn]);
    }
    for (int i = tid; i < 64 * 64; i += 256) {
        int nn = i >> 6, k = i & 63;
        uint32_t off = (uint32_t)nn * 128 + (((uint32_t)k * 2) ^ (((uint32_t)nn & 7) * 16));
        *(__half*)(smem + K1_W2 + off) = __float2half(W2[k * 64 + nn]);
        *(__half*)(smem + K1_W3 + off) = __float2half(W3[k * 64 + nn]);
    }
    for (int i = tid; i < 64; i += 256) {
        ((float*)(smem + K1_B1))[i] = b1[i];
        ((float*)(smem + K1_B2))[i] = b2[i];
        ((float*)(smem + K1_B3))[i] = b3[i];
    }
    __syncthreads();

    const float* sB1 = (const float*)(smem + K1_B1);
    const float* sB2 = (const float*)(smem + K1_B2);
    const float* sB3 = (const float*)(smem + K1_B3);

    int warp = tid >> 5, lane = tid & 31;
    char* sin = smem + K1_IN + warp * 2048;
    uint32_t sin_u = sb + K1_IN + (uint32_t)warp * 2048;

    int node0 = (blockIdx.x * 8 + warp) * 16;

    {
        int r = lane >> 1;
        int halfc = lane & 1;
        int nd = node0 + r;
        uint32_t off = (uint32_t)r * 128 + (((uint32_t)halfc * 16) ^ (((uint32_t)(r & 7)) * 16));
        uint4 v = make_uint4(0, 0, 0, 0);
        if (nd < n) {
            int b = __ldg(batch + nd);
            if (halfc == 0) {
                float2 a0 = *(const float2*)(x + (size_t)nd * 6);
                float2 a1 = *(const float2*)(x + (size_t)nd * 6 + 2);
                float2 a2 = *(const float2*)(x + (size_t)nd * 6 + 4);
                float2 u0 = *(const float2*)(u + (size_t)b * 4);
                v.x = pack_h2(a0.x, a0.y);
                v.y = pack_h2(a1.x, a1.y);
                v.z = pack_h2(a2.x, a2.y);
                v.w = pack_h2(u0.x, u0.y);
            } else {
                float2 u1 = *(const float2*)(u + (size_t)b * 4 + 2);
                v.x = pack_h2(u1.x, u1.y);
            }
        }
        *(uint4*)(sin + off) = v;
    }
    __syncwarp();

    int rowA = lane & 15;
    uint32_t aKx  = ((uint32_t)(lane >> 4)) * 16;
    uint32_t aXor = ((uint32_t)(rowA & 7)) * 16;
    int rowB = (lane & 7) + ((lane >> 4) & 1) * 8;
    uint32_t bKx  = ((uint32_t)((lane >> 3) & 1)) * 16;
    uint32_t bXor = ((uint32_t)(lane & 7)) * 16;
    int qr = lane >> 2;
    int qc = lane & 3;

    float d[8][4];
    uint32_t ax[4][4];

#pragma unroll
    for (int j = 0; j < 8; j++) { d[j][0] = 0.f; d[j][1] = 0.f; d[j][2] = 0.f; d[j][3] = 0.f; }
    {
        uint32_t a0, a1, a2, a3;
        ldsm4(a0, a1, a2, a3, sin_u + (uint32_t)rowA * 128 + (aKx ^ aXor));
#pragma unroll
        for (int jt = 0; jt < 4; jt++) {
            uint32_t b0, b1r, b2r, b3r;
            uint32_t baddr = sb + K1_W1 + (uint32_t)(jt * 16 + rowB) * 128 + (bKx ^ bXor);
            ldsm4(b0, b1r, b2r, b3r, baddr);
            mma_f16(d[2 * jt],     a0, a1, a2, a3, b0, b1r);
            mma_f16(d[2 * jt + 1], a0, a1, a2, a3, b2r, b3r);
        }
    }
#pragma unroll
    for (int kt = 0; kt < 4; kt++) {
        int j0 = 2 * kt, j1 = j0 + 1;
        float2 bv0 = *(const float2*)(sB1 + j0 * 8 + qc * 2);
        float2 bv1 = *(const float2*)(sB1 + j1 * 8 + qc * 2);
        ax[kt][0] = pack_h2(fmaxf(d[j0][0] + bv0.x, 0.f), fmaxf(d[j0][1] + bv0.y, 0.f));
        ax[kt][1] = pack_h2(fmaxf(d[j0][2] + bv0.x, 0.f), fmaxf(d[j0][3] + bv0.y, 0.f));
        ax[kt][2] = pack_h2(fmaxf(d[j1][0] + bv1.x, 0.f), fmaxf(d[j1][1] + bv1.y, 0.f));
        ax[kt][3] = pack_h2(fmaxf(d[j1][2] + bv1.x, 0.f), fmaxf(d[j1][3] + bv1.y, 0.f));
    }

#pragma unroll
    for (int j = 0; j < 8; j++) { d[j][0] = 0.f; d[j][1] = 0.f; d[j][2] = 0.f; d[j][3] = 0.f; }
#pragma unroll
    for (int kt = 0; kt < 4; kt++) {
#pragma unroll
        for (int jt = 0; jt < 4; jt++) {
            uint32_t b0, b1r, b2r, b3r;
            uint32_t baddr = sb + K1_W2 + (uint32_t)(jt * 16 + rowB) * 128
                           + (((uint32_t)kt * 32 + bKx) ^ bXor);
            ldsm4(b0, b1r, b2r, b3r, baddr);
            mma_f16(d[2 * jt],     ax[kt][0], ax[kt][1], ax[kt][2], ax[kt][3], b0, b1r);
            mma_f16(d[2 * jt + 1], ax[kt][0], ax[kt][1], ax[kt][2], ax[kt][3], b2r, b3r);
        }
    }
#pragma unroll
    for (int kt = 0; kt < 4; kt++) {
        int j0 = 2 * kt, j1 = j0 + 1;
        float2 bv0 = *(const float2*)(sB2 + j0 * 8 + qc * 2);
        float2 bv1 = *(const float2*)(sB2 + j1 * 8 + qc * 2);
        ax[kt][0] = pack_h2(fmaxf(d[j0][0] + bv0.x, 0.f), fmaxf(d[j0][1] + bv0.y, 0.f));
        ax[kt][1] = pack_h2(fmaxf(d[j0][2] + bv0.x, 0.f), fmaxf(d[j0][3] + bv0.y, 0.f));
        ax[kt][2] = pack_h2(fmaxf(d[j1][0] + bv1.x, 0.f), fmaxf(d[j1][1] + bv1.y, 0.f));
        ax[kt][3] = pack_h2(fmaxf(d[j1][2] + bv1.x, 0.f), fmaxf(d[j1][3] + bv1.y, 0.f));
    }

#pragma unroll
    for (int j = 0; j < 8; j++) { d[j][0] = 0.f; d[j][1] = 0.f; d[j][2] = 0.f; d[j][3] = 0.f; }
#pragma unroll
    for (int kt = 0; kt < 4; kt++) {
#pragma unroll
        for (int jt = 0; jt < 4; jt++) {
            uint32_t b0, b1r, b2r, b3r;
            uint32_t baddr = sb + K1_W3 + (uint32_t)(jt * 16 + rowB) * 128
                           + (((uint32_t)kt * 32 + bKx) ^ bXor);
            ldsm4(b0, b1r, b2r, b3r, baddr);
            mma_f16(d[2 * jt],     ax[kt][0], ax[kt][1], ax[kt][2], ax[kt][3], b0, b1r);
            mma_f16(d[2 * jt + 1], ax[kt][0], ax[kt][1], ax[kt][2], ax[kt][3], b2r, b3r);
        }
    }
    {
        __half2* Gh2 = (__half2*)g_h;
        int na = node0 + qr, nb = node0 + qr + 8;
#pragma unroll
        for (int j = 0; j < 8; j++) {
            float2 bv = *(const float2*)(sB3 + j * 8 + qc * 2);
            int fp = j * 4 + qc;
            if (na < n)
                Gh2[(size_t)na * 32 + fp] = __floats2half2_rn(d[j][0] + bv.x, d[j][1] + bv.y);
            if (nb < n)
                Gh2[(size_t)nb * 32 + fp] = __floats2half2_rn(d[j][2] + bv.x, d[j][3] + bv.y);
        }
    }
}

// ---------------------------------------------------------------------------
// K2: segment softmax stats + x_hyper materialization (EXACT R11 version:
// wide loads, next-iteration INDEX prefetch only).
// ---------------------------------------------------------------------------
__device__ __forceinline__ int lbound(const int* __restrict__ a, int n, int key)
{
    int lo = 0, hi = n;
    while (lo < hi) { int mid = (lo + hi) >> 1; if (a[mid] < key) lo = mid + 1; else hi = mid; }
    return lo;
}

__global__ __launch_bounds__(512)
void k_segstats(const int* __restrict__ hidx, const int* __restrict__ bh, int E,
                float* __restrict__ out, int writeBatch)
{
    __shared__ float sm_m[64][64];
    __shared__ float sm_s[64][64];

    int g = blockIdx.x;
    int lo = lbound(bh, E, g);
    int hi = lbound(bh, E, g + 1);

    int tid = threadIdx.x;
    int w = tid >> 5, lane = tid & 31;
    int j = lane >> 3;       // edge slot within warp (0..3)
    int c = lane & 7;        // 16B chunk (features c*8 .. c*8+7)

    const uint4* H4 = (const uint4*)g_h;
    uint4* XH4 = (uint4*)g_xh;

    float m[8], s[8];
#pragma unroll
    for (int q = 0; q < 8; q++) { m[q] = -3.0e38f; s[q] = 0.f; }

    int e = lo + w * 4 + j;
    int i0 = 0, i1 = 0, i2 = 0;
    if (e < hi) {
        i0 = __ldg(hidx + e); i1 = __ldg(hidx + E + e); i2 = __ldg(hidx + 2 * E + e);
    }
    while (e < hi) {
        int en = e + 64;
        int n0 = 0, n1 = 0, n2 = 0;
        if (en < hi) {
            n0 = __ldg(hidx + en); n1 = __ldg(hidx + E + en); n2 = __ldg(hidx + 2 * E + en);
        }
        uint4 va = H4[i0 * 8 + c];
        uint4 vb = H4[i1 * 8 + c];
        uint4 vc = H4[i2 * 8 + c];
        float xa[8], xb[8], xc[8], xv[8];
        h2x4_to_f8(va, xa); h2x4_to_f8(vb, xb); h2x4_to_f8(vc, xc);
#pragma unroll
        for (int q = 0; q < 8; q++) xv[q] = xa[q] + xb[q] + xc[q];
        uint4 o;
        o.x = pack_h2(xv[0], xv[1]); o.y = pack_h2(xv[2], xv[3]);
        o.z = pack_h2(xv[4], xv[5]); o.w = pack_h2(xv[6], xv[7]);
        XH4[(size_t)e * 8 + c] = o;
#pragma unroll
        for (int q = 0; q < 8; q++) {
            float xq = xv[q];
            if (xq > m[q]) { s[q] = s[q] * __expf(m[q] - xq) + 1.f; m[q] = xq; }
            else           { s[q] += __expf(xq - m[q]); }
        }
        e = en; i0 = n0; i1 = n1; i2 = n2;
    }

    if (writeBatch) {
        float gf = (float)g;
        for (int ee = lo + tid; ee < hi; ee += 512) out[E + ee] = gf;
    }

    int slot = w * 4 + j;     // 0..63
    *(float4*)&sm_m[slot][c * 8]     = make_float4(m[0], m[1], m[2], m[3]);
    *(float4*)&sm_m[slot][c * 8 + 4] = make_float4(m[4], m[5], m[6], m[7]);
    *(float4*)&sm_s[slot][c * 8]     = make_float4(s[0], s[1], s[2], s[3]);
    *(float4*)&sm_s[slot][c * 8 + 4] = make_float4(s[4], s[5], s[6], s[7]);
    __syncthreads();

    if (tid < 64) {
        int f = tid;
        float M = -3.0e38f;
#pragma unroll 8
        for (int sl = 0; sl < 64; sl++) M = fmaxf(M, sm_m[sl][f]);
        float S = 0.f;
#pragma unroll 8
        for (int sl = 0; sl < 64; sl++) {
            float mv = sm_m[sl][f];
            if (mv > -1.0e38f) S += sm_s[sl][f] * __expf(mv - M);
        }
        float R = (S > 0.f) ? (1.f / S) : 0.f;
        g_segmr[g * 64 + f] = make_float2(M, R);
    }
}

// ---------------------------------------------------------------------------
// K3: fp16 tensor-core main kernel — R11 engine + cp.async stat prefetch
// (stats for the next tile stream into per-warp smem during the GEMM phase;
// zero register cost).
// SMEM: weights/consts as before; per-warp sxh(2048) scf(2048) sst(512).
// ---------------------------------------------------------------------------
#define OFF_WT  0
#define OFF_V1  8192
#define OFF_V2  24576
#define OFF_C1  32768
#define OFF_C2  33024
#define OFF_V3  33280
#define OFF_C3  33536
#define OFF_WRP 33792
#define WRP_SZ  4608
#define SMEM_MAIN (OFF_WRP + 8 * WRP_SZ)   // 70656

__global__ __launch_bounds__(256, 2)
void k_main_mma(const int* __restrict__ bh,
                const float* __restrict__ Wt,
                const float* __restrict__ V1, const float* __restrict__ c1,
                const float* __restrict__ V2, const float* __restrict__ c2,
                const float* __restrict__ V3, const float* __restrict__ c3,
                float* __restrict__ out, int E)
{
    extern __shared__ __align__(128) char smem[];
    uint32_t sb = smem_u32(smem);
    int tid = threadIdx.x;

    // ---- stage weights as [n][k] fp16, xor-swizzled per row ----
    for (int i = tid; i < 64 * 64; i += 256) {
        int n = i >> 6, k = i & 63;
        uint32_t off = (uint32_t)n * 128 + (((uint32_t)k * 2) ^ (((uint32_t)n & 7) * 16));
        *(__half*)(smem + OFF_WT + off) = __float2half(Wt[k * 64 + n]);
        *(__half*)(smem + OFF_V2 + off) = __float2half(V2[k * 64 + n]);
    }
    for (int i = tid; i < 64 * 128; i += 256) {
        int n = i >> 7, k = i & 127;
        uint32_t off = (uint32_t)n * 256 + (((uint32_t)k * 2) ^ (((uint32_t)n & 7) * 16));
        *(__half*)(smem + OFF_V1 + off) = __float2half(V1[k * 64 + n]);
    }
    for (int i = tid; i < 64; i += 256) {
        ((float*)(smem + OFF_C1))[i] = c1[i];
        ((float*)(smem + OFF_C2))[i] = c2[i];
        ((float*)(smem + OFF_V3))[i] = V3[i];
    }
    if (tid == 0) *(float*)(smem + OFF_C3) = c3[0];
    __syncthreads();

    const float* sc1 = (const float*)(smem + OFF_C1);
    const float* sc2 = (const float*)(smem + OFF_C2);
    const float* sV3 = (const float*)(smem + OFF_V3);
    const float  c3v = *(const float*)(smem + OFF_C3);

    int warp = tid >> 5, lane = tid & 31;
    char* wbase = smem + OFF_WRP + warp * WRP_SZ;
    char* sxh  = wbase;          // 16 x 128B
    char* scf  = wbase + 2048;
    char* sst  = wbase + 4096;   // 512B stat buffer (next tile)
    uint32_t sxh_u = sb + OFF_WRP + (uint32_t)warp * WRP_SZ;
    uint32_t sst_u = sxh_u + 4096;

    // per-lane ldmatrix address components
    int rowA = lane & 15;
    uint32_t aOff = (uint32_t)rowA * 128;
    uint32_t aKx  = ((uint32_t)(lane >> 4)) * 16;
    uint32_t aXor = ((uint32_t)(rowA & 7)) * 16;

    int rowB = (lane & 7) + ((lane >> 4) & 1) * 8;
    uint32_t bKx  = ((uint32_t)((lane >> 3) & 1)) * 16;
    uint32_t bXor = ((uint32_t)(lane & 7)) * 16;

    int qr = lane >> 2;
    int qc = lane & 3;
    uint32_t qxor = (uint32_t)qr * 16;

    // wide-staging lane mapping
    int sc_ = lane & 7;             // 16B chunk (features sc_*8..sc_*8+7)
    int srow = lane >> 3;           // row offset within 4-row pass

    int ngrp = (E + 15) >> 4;
    int gwid = blockIdx.x * 8 + warp;
    int nwrp = gridDim.x * 8;

    // prefetch state for the upcoming tile
    uint4 pv0, pv1, pv2, pv3;
    int pg0 = 0, pglast = 0;

    // prologue prefetch
    if (gwid < ngrp) {
        int e0 = gwid << 4;
        const uint4* xin4 = (const uint4*)(g_xh + (size_t)e0 * 64);
        int r0 = srow, r1 = 4 + srow, r2 = 8 + srow, r3 = 12 + srow;
        pv0 = (e0 + r0 < E) ? xin4[r0 * 8 + sc_] : make_uint4(0, 0, 0, 0);
        pv1 = (e0 + r1 < E) ? xin4[r1 * 8 + sc_] : make_uint4(0, 0, 0, 0);
        pv2 = (e0 + r2 < E) ? xin4[r2 * 8 + sc_] : make_uint4(0, 0, 0, 0);
        pv3 = (e0 + r3 < E) ? xin4[r3 * 8 + sc_] : make_uint4(0, 0, 0, 0);
        pg0 = __ldg(bh + e0);
        pglast = __ldg(bh + min(e0 + 15, E - 1));
        if (pg0 == pglast)
            cp_async16(sst_u + (uint32_t)lane * 16,
                       (const char*)(g_segmr + (size_t)pg0 * 64) + lane * 16);
        cp_async_commit();
    }

    for (int grp = gwid; grp < ngrp; grp += nwrp) {
        int e0 = grp << 4;
        cp_async_wait_all();
        __syncwarp();

        // ---- stage from prefetched registers ----
        if (pg0 == pglast) {
            // fast path: whole tile one graph — stats from smem (cp.async'd)
            const float4* st = (const float4*)(sst + sc_ * 64);
            float4 s01 = st[0], s23 = st[1], s45 = st[2], s67 = st[3];
            uint4 vv[4] = { pv0, pv1, pv2, pv3 };
#pragma unroll
            for (int p = 0; p < 4; p++) {
                int row = p * 4 + srow;
                float xv[8];
                h2x4_to_f8(vv[p], xv);
                uint4 cfv;
                cfv.x = pack_h2(__expf(xv[0] - s01.x) * s01.y, __expf(xv[1] - s01.z) * s01.w);
                cfv.y = pack_h2(__expf(xv[2] - s23.x) * s23.y, __expf(xv[3] - s23.z) * s23.w);
                cfv.z = pack_h2(__expf(xv[4] - s45.x) * s45.y, __expf(xv[5] - s45.z) * s45.w);
                cfv.w = pack_h2(__expf(xv[6] - s67.x) * s67.y, __expf(xv[7] - s67.z) * s67.w);
                uint32_t off = (uint32_t)row * 128 +
                               (((uint32_t)sc_ * 16) ^ (((uint32_t)(row & 7)) * 16));
                *(uint4*)(sxh + off) = vv[p];
                *(uint4*)(scf + off) = cfv;
            }
        } else {
            // slow path: write xh tiles first, then per-edge cf from smem
            uint4 vv[4] = { pv0, pv1, pv2, pv3 };
#pragma unroll
            for (int p = 0; p < 4; p++) {
                int row = p * 4 + srow;
                uint32_t off = (uint32_t)row * 128 +
                               (((uint32_t)sc_ * 16) ^ (((uint32_t)(row & 7)) * 16));
                *(uint4*)(sxh + off) = vv[p];
            }
            __syncwarp();
#pragma unroll 4
            for (int it = 0; it < 16; it++) {
                int e = e0 + it;
                uint32_t off = (uint32_t)it * 128 + (((uint32_t)lane * 4) ^ (((uint32_t)it & 7) * 16));
                if (e < E) {
                    int g = __ldg(bh + e);
                    __half2 xh2 = *(__half2*)(sxh + off);
                    float2 xv = __half22float2(xh2);
                    float4 mr = *(const float4*)(g_segmr + (size_t)g * 64 + 2 * lane);
                    float cfa = __expf(xv.x - mr.x) * mr.y;
                    float cfb = __expf(xv.y - mr.z) * mr.w;
                    *(__half2*)(scf + off) = __floats2half2_rn(cfa, cfb);
                } else {
                    *(__half2*)(scf + off) = __floats2half2_rn(0.f, 0.f);
                }
            }
        }
        __syncwarp();

        // ---- issue prefetch for next tile (hidden under the GEMM phase) ----
        int nxt = grp + nwrp;
        if (nxt < ngrp) {
            int ne0 = nxt << 4;
            const uint4* xin4 = (const uint4*)(g_xh + (size_t)ne0 * 64);
            int r0 = srow, r1 = 4 + srow, r2 = 8 + srow, r3 = 12 + srow;
            pv0 = (ne0 + r0 < E) ? xin4[r0 * 8 + sc_] : make_uint4(0, 0, 0, 0);
            pv1 = (ne0 + r1 < E) ? xin4[r1 * 8 + sc_] : make_uint4(0, 0, 0, 0);
            pv2 = (ne0 + r2 < E) ? xin4[r2 * 8 + sc_] : make_uint4(0, 0, 0, 0);
            pv3 = (ne0 + r3 < E) ? xin4[r3 * 8 + sc_] : make_uint4(0, 0, 0, 0);
            pg0 = __ldg(bh + ne0);
            pglast = __ldg(bh + min(ne0 + 15, E - 1));
            if (pg0 == pglast)
                cp_async16(sst_u + (uint32_t)lane * 16,
                           (const char*)(g_segmr + (size_t)pg0 * 64) + lane * 16);
            cp_async_commit();
        }

        float d[8][4];
        uint32_t axh[4][4];    // A-frags of xh (k 0..63), reused by GEMM1+GEMM2
        uint32_t ax2[4][4];    // A-frags of xhh (GEMM2 k 64..127), then o1 (GEMM3)

        // ================= GEMM1: D = xh @ weight =================
#pragma unroll
        for (int j = 0; j < 8; j++) { d[j][0] = 0.f; d[j][1] = 0.f; d[j][2] = 0.f; d[j][3] = 0.f; }
#pragma unroll
        for (int kt = 0; kt < 4; kt++) {
            ldsm4(axh[kt][0], axh[kt][1], axh[kt][2], axh[kt][3],
                  sxh_u + aOff + (((uint32_t)kt * 32 + aKx) ^ aXor));
#pragma unroll
            for (int jt = 0; jt < 4; jt++) {
                uint32_t b0, b1, b2, b3;
                uint32_t baddr = sb + OFF_WT + (uint32_t)(jt * 16 + rowB) * 128
                               + (((uint32_t)kt * 32 + bKx) ^ bXor);
                ldsm4(b0, b1, b2, b3, baddr);
                mma_f16(d[2 * jt],     axh[kt][0], axh[kt][1], axh[kt][2], axh[kt][3], b0, b1);
                mma_f16(d[2 * jt + 1], axh[kt][0], axh[kt][1], axh[kt][2], axh[kt][3], b2, b3);
            }
        }
        // epi1 (in registers): xhh = cf * relu(D) -> A-frags for GEMM2 k 64..127
#pragma unroll
        for (int kt = 0; kt < 4; kt++) {
            int j0 = 2 * kt, j1 = j0 + 1;
            uint32_t o00 = (uint32_t)qr * 128 + (((uint32_t)(j0 * 16 + qc * 4)) ^ qxor);
            uint32_t o10 = (uint32_t)qr * 128 + (((uint32_t)(j1 * 16 + qc * 4)) ^ qxor);
            float2 cfa = __half22float2(*(__half2*)(scf + o00));
            float2 cfb = __half22float2(*(__half2*)(scf + o00 + 1024));
            float2 cfc = __half22float2(*(__half2*)(scf + o10));
            float2 cfd = __half22float2(*(__half2*)(scf + o10 + 1024));
            ax2[kt][0] = pack_h2(fmaxf(d[j0][0], 0.f) * cfa.x, fmaxf(d[j0][1], 0.f) * cfa.y);
            ax2[kt][1] = pack_h2(fmaxf(d[j0][2], 0.f) * cfb.x, fmaxf(d[j0][3], 0.f) * cfb.y);
            ax2[kt][2] = pack_h2(fmaxf(d[j1][0], 0.f) * cfc.x, fmaxf(d[j1][1], 0.f) * cfc.y);
            ax2[kt][3] = pack_h2(fmaxf(d[j1][2], 0.f) * cfd.x, fmaxf(d[j1][3], 0.f) * cfd.y);
        }

        // ================= GEMM2: D = [xh | xhh] @ V1 =================
#pragma unroll
        for (int j = 0; j < 8; j++) { d[j][0] = 0.f; d[j][1] = 0.f; d[j][2] = 0.f; d[j][3] = 0.f; }
#pragma unroll
        for (int kt = 0; kt < 8; kt++) {
            const uint32_t* a = (kt < 4) ? axh[kt] : ax2[kt - 4];
#pragma unroll
            for (int jt = 0; jt < 4; jt++) {
                uint32_t b0, b1, b2, b3;
                uint32_t baddr = sb + OFF_V1 + (uint32_t)(jt * 16 + rowB) * 256
                               + (((uint32_t)kt * 32 + bKx) ^ bXor);
                ldsm4(b0, b1, b2, b3, baddr);
                mma_f16(d[2 * jt],     a[0], a[1], a[2], a[3], b0, b1);
                mma_f16(d[2 * jt + 1], a[0], a[1], a[2], a[3], b2, b3);
            }
        }
        // epi2 (in registers): o1 = relu(D + c1) -> A-frags for GEMM3
#pragma unroll
        for (int kt = 0; kt < 4; kt++) {
            int j0 = 2 * kt, j1 = j0 + 1;
            float2 bv0 = *(const float2*)(sc1 + j0 * 8 + qc * 2);
            float2 bv1 = *(const float2*)(sc1 + j1 * 8 + qc * 2);
            ax2[kt][0] = pack_h2(fmaxf(d[j0][0] + bv0.x, 0.f), fmaxf(d[j0][1] + bv0.y, 0.f));
            ax2[kt][1] = pack_h2(fmaxf(d[j0][2] + bv0.x, 0.f), fmaxf(d[j0][3] + bv0.y, 0.f));
            ax2[kt][2] = pack_h2(fmaxf(d[j1][0] + bv1.x, 0.f), fmaxf(d[j1][1] + bv1.y, 0.f));
            ax2[kt][3] = pack_h2(fmaxf(d[j1][2] + bv1.x, 0.f), fmaxf(d[j1][3] + bv1.y, 0.f));
        }

        // ================= GEMM3: D = o1 @ V2 =================
#pragma unroll
        for (int j = 0; j < 8; j++) { d[j][0] = 0.f; d[j][1] = 0.f; d[j][2] = 0.f; d[j][3] = 0.f; }
#pragma unroll
        for (int kt = 0; kt < 4; kt++) {
#pragma unroll
            for (int jt = 0; jt < 4; jt++) {
                uint32_t b0, b1, b2, b3;
                uint32_t baddr = sb + OFF_V2 + (uint32_t)(jt * 16 + rowB) * 128
                               + (((uint32_t)kt * 32 + bKx) ^ bXor);
                ldsm4(b0, b1, b2, b3, baddr);
                mma_f16(d[2 * jt],     ax2[kt][0], ax2[kt][1], ax2[kt][2], ax2[kt][3], b0, b1);
                mma_f16(d[2 * jt + 1], ax2[kt][0], ax2[kt][1], ax2[kt][2], ax2[kt][3], b2, b3);
            }
        }
        // epi3: o2 = relu(D + c2); z = o2 . V3 + c3; out = sigmoid(z)
        float zlo = 0.f, zhi = 0.f;
#pragma unroll
        for (int j = 0; j < 8; j++) {
            int col = j * 8 + qc * 2;
            float2 bv = *(const float2*)(sc2 + col);
            float2 wv = *(const float2*)(sV3 + col);
            zlo = fmaf(fmaxf(d[j][0] + bv.x, 0.f), wv.x, zlo);
            zlo = fmaf(fmaxf(d[j][1] + bv.y, 0.f), wv.y, zlo);
            zhi = fmaf(fmaxf(d[j][2] + bv.x, 0.f), wv.x, zhi);
            zhi = fmaf(fmaxf(d[j][3] + bv.y, 0.f), wv.y, zhi);
        }
        zlo += __shfl_xor_sync(0xffffffffu, zlo, 1);
        zlo += __shfl_xor_sync(0xffffffffu, zlo, 2);
        zhi += __shfl_xor_sync(0xffffffffu, zhi, 1);
        zhi += __shfl_xor_sync(0xffffffffu, zhi, 2);
        if (qc == 0) {
            int ea = e0 + qr, eb = e0 + qr + 8;
            if (ea < E) out[ea] = 1.f / (1.f + __expf(-(zlo + c3v)));
            if (eb < E) out[eb] = 1.f / (1.f + __expf(-(zhi + c3v)));
        }
    }
}

// ---------------------------------------------------------------------------
// kernel_launch
// ---------------------------------------------------------------------------
extern "C" void kernel_launch(void* const* d_in, const int* in_sizes, int n_in,
                              void* d_out, int out_size)
{
    const float* x     = (const float*)d_in[0];
    const float* u     = (const float*)d_in[1];
    const int*   batch = (const int*)d_in[2];
    const int*   hidx  = (const int*)d_in[3];
    const int*   bh    = (const int*)d_in[4];

    int N = in_sizes[0] / 6;
    int G = in_sizes[1] / 4;
    int E = in_sizes[4];

    int wb = (in_sizes[5] == 1) ? 6 : 5;   // skip scalar "r" if present
    const float* W1 = (const float*)d_in[wb + 0];
    const float* b1 = (const float*)d_in[wb + 1];
    const float* W2 = (const float*)d_in[wb + 2];
    const float* b2 = (const float*)d_in[wb + 3];
    const float* W3 = (const float*)d_in[wb + 4];
    const float* b3 = (const float*)d_in[wb + 5];
    const float* Wt = (const float*)d_in[wb + 6];
    const float* V1 = (const float*)d_in[wb + 7];
    const float* c1 = (const float*)d_in[wb + 8];
    const float* V2 = (const float*)d_in[wb + 9];
    const float* c2 = (const float*)d_in[wb + 10];
    const float* V3 = (const float*)d_in[wb + 11];
    const float* c3 = (const float*)d_in[wb + 12];

    int writeBatch = (out_size >= 2 * E) ? 1 : 0;

    cudaFuncSetAttribute(k_node_mlp_mma, cudaFuncAttributeMaxDynamicSharedMemorySize, K1_SMEM);
    k_node_mlp_mma<<<(N + 127) / 128, 256, K1_SMEM>>>(x, u, batch, W1, b1, W2, b2, W3, b3, N);

    k_segstats<<<G, 512>>>(hidx, bh, E, (float*)d_out, writeBatch);

    int nsm = 148;
    cudaDeviceGetAttribute(&nsm, cudaDevAttrMultiProcessorCount, 0);
    cudaFuncSetAttribute(k_main_mma, cudaFuncAttributeMaxDynamicSharedMemorySize, SMEM_MAIN);
    k_main_mma<<<nsm * 2, 256, SMEM_MAIN>>>(bh, Wt, V1, c1, V2, c2, V3, c3,
                                            (float*)d_out, E);
}

// round 15
// speedup vs baseline: 1.2668x; 1.0412x over previous
#include <cuda_runtime.h>
#include <cuda_fp16.h>
#include <cstdint>
#include <math.h>

// Problem constants (fixed shapes for this registry entry)
#define NMAX 32768
#define GMAX 2048
#define EMAX 1146880

// Scratch (no cudaMalloc allowed)
__device__ __half  g_h[NMAX * 64];         // node embeddings fp16 [N,64] (4 MB)
__device__ float2  g_segmr[GMAX * 64];     // per-graph per-feature (max, 1/sum)
__device__ __half  g_xh[(size_t)EMAX * 64];// hyperedge features, fp16 (147 MB)

// ---------------------------------------------------------------------------
// PTX wrappers (portable tensor path: ldmatrix + mma.sync, compute_103-safe)
// ---------------------------------------------------------------------------
__device__ __forceinline__ uint32_t smem_u32(const void* p) {
    uint32_t a;
    asm("{ .reg .u64 t; cvta.to.shared.u64 t, %1; cvt.u32.u64 %0, t; }" : "=r"(a) : "l"(p));
    return a;
}
__device__ __forceinline__ void ldsm4(uint32_t& r0, uint32_t& r1, uint32_t& r2, uint32_t& r3,
                                      uint32_t addr) {
    asm volatile("ldmatrix.sync.aligned.m8n8.x4.shared.b16 {%0,%1,%2,%3}, [%4];"
                 : "=r"(r0), "=r"(r1), "=r"(r2), "=r"(r3) : "r"(addr));
}
__device__ __forceinline__ void mma_f16(float d[4], uint32_t a0, uint32_t a1, uint32_t a2,
                                        uint32_t a3, uint32_t b0, uint32_t b1) {
    asm volatile(
        "mma.sync.aligned.m16n8k16.row.col.f32.f16.f16.f32 "
        "{%0,%1,%2,%3},{%4,%5,%6,%7},{%8,%9},{%0,%1,%2,%3};"
        : "+f"(d[0]), "+f"(d[1]), "+f"(d[2]), "+f"(d[3])
        : "r"(a0), "r"(a1), "r"(a2), "r"(a3), "r"(b0), "r"(b1));
}
__device__ __forceinline__ uint32_t pack_h2(float lo, float hi) {
    uint32_t r;
    asm("cvt.rn.f16x2.f32 %0, %1, %2;" : "=r"(r) : "f"(hi), "f"(lo));
    return r;
}
__device__ __forceinline__ void h2x4_to_f8(uint4 v, float* x) {
    float2 t;
    t = __half22float2(*(__half2*)&v.x); x[0] = t.x; x[1] = t.y;
    t = __half22float2(*(__half2*)&v.y); x[2] = t.x; x[3] = t.y;
    t = __half22float2(*(__half2*)&v.z); x[4] = t.x; x[5] = t.y;
    t = __half22float2(*(__half2*)&v.w); x[6] = t.x; x[7] = t.y;
}

// ---------------------------------------------------------------------------
// K1: node MLP via fp16 MMA. 512-thread blocks (16 warps, 256 nodes/block),
// float4-vectorized weight staging (4 n-columns per load).
// ---------------------------------------------------------------------------
#define K1_W1   0
#define K1_W2   8192
#define K1_W3   16384
#define K1_B1   24576
#define K1_B2   24832
#define K1_B3   25088
#define K1_IN   25344
#define K1_SMEM (K1_IN + 16 * 2048)   // 58112

__global__ __launch_bounds__(512)
void k_node_mlp_mma(const float* __restrict__ x, const float* __restrict__ u,
                    const int* __restrict__ batch,
                    const float* __restrict__ W1, const float* __restrict__ b1,
                    const float* __restrict__ W2, const float* __restrict__ b2,
                    const float* __restrict__ W3, const float* __restrict__ b3,
                    int n)
{
    extern __shared__ __align__(128) char smem[];
    uint32_t sb = smem_u32(smem);
    int tid = threadIdx.x;

    // stage W1 [16k x 64n] -> [n][k] rows, swizzled; vectorized over n (4 cols/load)
    for (int i = tid; i < 16 * 16; i += 512) {
        int k = i >> 4, n4 = (i & 15) * 4;
        float4 wv = *(const float4*)(W1 + k * 64 + n4);
#pragma unroll
        for (int q = 0; q < 4; q++) {
            int nn = n4 + q;
            uint32_t off = (uint32_t)nn * 128 + (((uint32_t)k * 2) ^ (((uint32_t)nn & 7) * 16));
            *(__half*)(smem + K1_W1 + off) = __float2half(((const float*)&wv)[q]);
        }
    }
    // stage W2, W3 [64k x 64n] -> [n][k] 128B rows, swizzled; vectorized over n
    for (int i = tid; i < 64 * 16; i += 512) {
        int k = i >> 4, n4 = (i & 15) * 4;
        float4 w2 = *(const float4*)(W2 + k * 64 + n4);
        float4 w3 = *(const float4*)(W3 + k * 64 + n4);
#pragma unroll
        for (int q = 0; q < 4; q++) {
            int nn = n4 + q;
            uint32_t off = (uint32_t)nn * 128 + (((uint32_t)k * 2) ^ (((uint32_t)nn & 7) * 16));
            *(__half*)(smem + K1_W2 + off) = __float2half(((const float*)&w2)[q]);
            *(__half*)(smem + K1_W3 + off) = __float2half(((const float*)&w3)[q]);
        }
    }
    for (int i = tid; i < 64; i += 512) {
        ((float*)(smem + K1_B1))[i] = b1[i];
        ((float*)(smem + K1_B2))[i] = b2[i];
        ((float*)(smem + K1_B3))[i] = b3[i];
    }
    __syncthreads();

    const float* sB1 = (const float*)(smem + K1_B1);
    const float* sB2 = (const float*)(smem + K1_B2);
    const float* sB3 = (const float*)(smem + K1_B3);

    int warp = tid >> 5, lane = tid & 31;
    char* sin = smem + K1_IN + warp * 2048;
    uint32_t sin_u = sb + K1_IN + (uint32_t)warp * 2048;

    int node0 = (blockIdx.x * 16 + warp) * 16;

    {
        int r = lane >> 1;
        int halfc = lane & 1;
        int nd = node0 + r;
        uint32_t off = (uint32_t)r * 128 + (((uint32_t)halfc * 16) ^ (((uint32_t)(r & 7)) * 16));
        uint4 v = make_uint4(0, 0, 0, 0);
        if (nd < n) {
            int b = __ldg(batch + nd);
            if (halfc == 0) {
                float2 a0 = *(const float2*)(x + (size_t)nd * 6);
                float2 a1 = *(const float2*)(x + (size_t)nd * 6 + 2);
                float2 a2 = *(const float2*)(x + (size_t)nd * 6 + 4);
                float2 u0 = *(const float2*)(u + (size_t)b * 4);
                v.x = pack_h2(a0.x, a0.y);
                v.y = pack_h2(a1.x, a1.y);
                v.z = pack_h2(a2.x, a2.y);
                v.w = pack_h2(u0.x, u0.y);
            } else {
                float2 u1 = *(const float2*)(u + (size_t)b * 4 + 2);
                v.x = pack_h2(u1.x, u1.y);
            }
        }
        *(uint4*)(sin + off) = v;
    }
    __syncwarp();

    int rowA = lane & 15;
    uint32_t aKx  = ((uint32_t)(lane >> 4)) * 16;
    uint32_t aXor = ((uint32_t)(rowA & 7)) * 16;
    int rowB = (lane & 7) + ((lane >> 4) & 1) * 8;
    uint32_t bKx  = ((uint32_t)((lane >> 3) & 1)) * 16;
    uint32_t bXor = ((uint32_t)(lane & 7)) * 16;
    int qr = lane >> 2;
    int qc = lane & 3;

    float d[8][4];
    uint32_t ax[4][4];

#pragma unroll
    for (int j = 0; j < 8; j++) { d[j][0] = 0.f; d[j][1] = 0.f; d[j][2] = 0.f; d[j][3] = 0.f; }
    {
        uint32_t a0, a1, a2, a3;
        ldsm4(a0, a1, a2, a3, sin_u + (uint32_t)rowA * 128 + (aKx ^ aXor));
#pragma unroll
        for (int jt = 0; jt < 4; jt++) {
            uint32_t b0, b1r, b2r, b3r;
            uint32_t baddr = sb + K1_W1 + (uint32_t)(jt * 16 + rowB) * 128 + (bKx ^ bXor);
            ldsm4(b0, b1r, b2r, b3r, baddr);
            mma_f16(d[2 * jt],     a0, a1, a2, a3, b0, b1r);
            mma_f16(d[2 * jt + 1], a0, a1, a2, a3, b2r, b3r);
        }
    }
#pragma unroll
    for (int kt = 0; kt < 4; kt++) {
        int j0 = 2 * kt, j1 = j0 + 1;
        float2 bv0 = *(const float2*)(sB1 + j0 * 8 + qc * 2);
        float2 bv1 = *(const float2*)(sB1 + j1 * 8 + qc * 2);
        ax[kt][0] = pack_h2(fmaxf(d[j0][0] + bv0.x, 0.f), fmaxf(d[j0][1] + bv0.y, 0.f));
        ax[kt][1] = pack_h2(fmaxf(d[j0][2] + bv0.x, 0.f), fmaxf(d[j0][3] + bv0.y, 0.f));
        ax[kt][2] = pack_h2(fmaxf(d[j1][0] + bv1.x, 0.f), fmaxf(d[j1][1] + bv1.y, 0.f));
        ax[kt][3] = pack_h2(fmaxf(d[j1][2] + bv1.x, 0.f), fmaxf(d[j1][3] + bv1.y, 0.f));
    }

#pragma unroll
    for (int j = 0; j < 8; j++) { d[j][0] = 0.f; d[j][1] = 0.f; d[j][2] = 0.f; d[j][3] = 0.f; }
#pragma unroll
    for (int kt = 0; kt < 4; kt++) {
#pragma unroll
        for (int jt = 0; jt < 4; jt++) {
            uint32_t b0, b1r, b2r, b3r;
            uint32_t baddr = sb + K1_W2 + (uint32_t)(jt * 16 + rowB) * 128
                           + (((uint32_t)kt * 32 + bKx) ^ bXor);
            ldsm4(b0, b1r, b2r, b3r, baddr);
            mma_f16(d[2 * jt],     ax[kt][0], ax[kt][1], ax[kt][2], ax[kt][3], b0, b1r);
            mma_f16(d[2 * jt + 1], ax[kt][0], ax[kt][1], ax[kt][2], ax[kt][3], b2r, b3r);
        }
    }
#pragma unroll
    for (int kt = 0; kt < 4; kt++) {
        int j0 = 2 * kt, j1 = j0 + 1;
        float2 bv0 = *(const float2*)(sB2 + j0 * 8 + qc * 2);
        float2 bv1 = *(const float2*)(sB2 + j1 * 8 + qc * 2);
        ax[kt][0] = pack_h2(fmaxf(d[j0][0] + bv0.x, 0.f), fmaxf(d[j0][1] + bv0.y, 0.f));
        ax[kt][1] = pack_h2(fmaxf(d[j0][2] + bv0.x, 0.f), fmaxf(d[j0][3] + bv0.y, 0.f));
        ax[kt][2] = pack_h2(fmaxf(d[j1][0] + bv1.x, 0.f), fmaxf(d[j1][1] + bv1.y, 0.f));
        ax[kt][3] = pack_h2(fmaxf(d[j1][2] + bv1.x, 0.f), fmaxf(d[j1][3] + bv1.y, 0.f));
    }

#pragma unroll
    for (int j = 0; j < 8; j++) { d[j][0] = 0.f; d[j][1] = 0.f; d[j][2] = 0.f; d[j][3] = 0.f; }
#pragma unroll
    for (int kt = 0; kt < 4; kt++) {
#pragma unroll
        for (int jt = 0; jt < 4; jt++) {
            uint32_t b0, b1r, b2r, b3r;
            uint32_t baddr = sb + K1_W3 + (uint32_t)(jt * 16 + rowB) * 128
                           + (((uint32_t)kt * 32 + bKx) ^ bXor);
            ldsm4(b0, b1r, b2r, b3r, baddr);
            mma_f16(d[2 * jt],     ax[kt][0], ax[kt][1], ax[kt][2], ax[kt][3], b0, b1r);
            mma_f16(d[2 * jt + 1], ax[kt][0], ax[kt][1], ax[kt][2], ax[kt][3], b2r, b3r);
        }
    }
    {
        __half2* Gh2 = (__half2*)g_h;
        int na = node0 + qr, nb = node0 + qr + 8;
#pragma unroll
        for (int j = 0; j < 8; j++) {
            float2 bv = *(const float2*)(sB3 + j * 8 + qc * 2);
            int fp = j * 4 + qc;
            if (na < n)
                Gh2[(size_t)na * 32 + fp] = __floats2half2_rn(d[j][0] + bv.x, d[j][1] + bv.y);
            if (nb < n)
                Gh2[(size_t)nb * 32 + fp] = __floats2half2_rn(d[j][2] + bv.x, d[j][3] + bv.y);
        }
    }
}

// ---------------------------------------------------------------------------
// K2: segment softmax stats + x_hyper materialization (EXACT R11 version:
// wide loads, next-iteration INDEX prefetch only).
// ---------------------------------------------------------------------------
__device__ __forceinline__ int lbound(const int* __restrict__ a, int n, int key)
{
    int lo = 0, hi = n;
    while (lo < hi) { int mid = (lo + hi) >> 1; if (a[mid] < key) lo = mid + 1; else hi = mid; }
    return lo;
}

__global__ __launch_bounds__(512)
void k_segstats(const int* __restrict__ hidx, const int* __restrict__ bh, int E,
                float* __restrict__ out, int writeBatch)
{
    __shared__ float sm_m[64][64];
    __shared__ float sm_s[64][64];

    int g = blockIdx.x;
    int lo = lbound(bh, E, g);
    int hi = lbound(bh, E, g + 1);

    int tid = threadIdx.x;
    int w = tid >> 5, lane = tid & 31;
    int j = lane >> 3;       // edge slot within warp (0..3)
    int c = lane & 7;        // 16B chunk (features c*8 .. c*8+7)

    const uint4* H4 = (const uint4*)g_h;
    uint4* XH4 = (uint4*)g_xh;

    float m[8], s[8];
#pragma unroll
    for (int q = 0; q < 8; q++) { m[q] = -3.0e38f; s[q] = 0.f; }

    int e = lo + w * 4 + j;
    int i0 = 0, i1 = 0, i2 = 0;
    if (e < hi) {
        i0 = __ldg(hidx + e); i1 = __ldg(hidx + E + e); i2 = __ldg(hidx + 2 * E + e);
    }
    while (e < hi) {
        int en = e + 64;
        int n0 = 0, n1 = 0, n2 = 0;
        if (en < hi) {
            n0 = __ldg(hidx + en); n1 = __ldg(hidx + E + en); n2 = __ldg(hidx + 2 * E + en);
        }
        uint4 va = H4[i0 * 8 + c];
        uint4 vb = H4[i1 * 8 + c];
        uint4 vc = H4[i2 * 8 + c];
        float xa[8], xb[8], xc[8], xv[8];
        h2x4_to_f8(va, xa); h2x4_to_f8(vb, xb); h2x4_to_f8(vc, xc);
#pragma unroll
        for (int q = 0; q < 8; q++) xv[q] = xa[q] + xb[q] + xc[q];
        uint4 o;
        o.x = pack_h2(xv[0], xv[1]); o.y = pack_h2(xv[2], xv[3]);
        o.z = pack_h2(xv[4], xv[5]); o.w = pack_h2(xv[6], xv[7]);
        XH4[(size_t)e * 8 + c] = o;
#pragma unroll
        for (int q = 0; q < 8; q++) {
            float xq = xv[q];
            if (xq > m[q]) { s[q] = s[q] * __expf(m[q] - xq) + 1.f; m[q] = xq; }
            else           { s[q] += __expf(xq - m[q]); }
        }
        e = en; i0 = n0; i1 = n1; i2 = n2;
    }

    if (writeBatch) {
        float gf = (float)g;
        for (int ee = lo + tid; ee < hi; ee += 512) out[E + ee] = gf;
    }

    int slot = w * 4 + j;     // 0..63
    *(float4*)&sm_m[slot][c * 8]     = make_float4(m[0], m[1], m[2], m[3]);
    *(float4*)&sm_m[slot][c * 8 + 4] = make_float4(m[4], m[5], m[6], m[7]);
    *(float4*)&sm_s[slot][c * 8]     = make_float4(s[0], s[1], s[2], s[3]);
    *(float4*)&sm_s[slot][c * 8 + 4] = make_float4(s[4], s[5], s[6], s[7]);
    __syncthreads();

    if (tid < 64) {
        int f = tid;
        float M = -3.0e38f;
#pragma unroll 8
        for (int sl = 0; sl < 64; sl++) M = fmaxf(M, sm_m[sl][f]);
        float S = 0.f;
#pragma unroll 8
        for (int sl = 0; sl < 64; sl++) {
            float mv = sm_m[sl][f];
            if (mv > -1.0e38f) S += sm_s[sl][f] * __expf(mv - M);
        }
        float R = (S > 0.f) ? (1.f / S) : 0.f;
        g_segmr[g * 64 + f] = make_float2(M, R);
    }
}

// ---------------------------------------------------------------------------
// K3: fp16 tensor-core main kernel — EXACT R11 champion version.
// ---------------------------------------------------------------------------
#define OFF_WT  0
#define OFF_V1  8192
#define OFF_V2  24576
#define OFF_C1  32768
#define OFF_C2  33024
#define OFF_V3  33280
#define OFF_C3  33536
#define OFF_WRP 33792
#define WRP_SZ  4096
#define SMEM_MAIN (OFF_WRP + 8 * WRP_SZ)   // 66560

__global__ __launch_bounds__(256, 2)
void k_main_mma(const int* __restrict__ bh,
                const float* __restrict__ Wt,
                const float* __restrict__ V1, const float* __restrict__ c1,
                const float* __restrict__ V2, const float* __restrict__ c2,
                const float* __restrict__ V3, const float* __restrict__ c3,
                float* __restrict__ out, int E)
{
    extern __shared__ __align__(128) char smem[];
    uint32_t sb = smem_u32(smem);
    int tid = threadIdx.x;

    // ---- stage weights as [n][k] fp16, xor-swizzled per row ----
    for (int i = tid; i < 64 * 64; i += 256) {
        int n = i >> 6, k = i & 63;
        uint32_t off = (uint32_t)n * 128 + (((uint32_t)k * 2) ^ (((uint32_t)n & 7) * 16));
        *(__half*)(smem + OFF_WT + off) = __float2half(Wt[k * 64 + n]);
        *(__half*)(smem + OFF_V2 + off) = __float2half(V2[k * 64 + n]);
    }
    for (int i = tid; i < 64 * 128; i += 256) {
        int n = i >> 7, k = i & 127;
        uint32_t off = (uint32_t)n * 256 + (((uint32_t)k * 2) ^ (((uint32_t)n & 7) * 16));
        *(__half*)(smem + OFF_V1 + off) = __float2half(V1[k * 64 + n]);
    }
    for (int i = tid; i < 64; i += 256) {
        ((float*)(smem + OFF_C1))[i] = c1[i];
        ((float*)(smem + OFF_C2))[i] = c2[i];
        ((float*)(smem + OFF_V3))[i] = V3[i];
    }
    if (tid == 0) *(float*)(smem + OFF_C3) = c3[0];
    __syncthreads();

    const float* sc1 = (const float*)(smem + OFF_C1);
    const float* sc2 = (const float*)(smem + OFF_C2);
    const float* sV3 = (const float*)(smem + OFF_V3);
    const float  c3v = *(const float*)(smem + OFF_C3);

    int warp = tid >> 5, lane = tid & 31;
    char* wbase = smem + OFF_WRP + warp * WRP_SZ;
    char* sxh  = wbase;          // 16 x 128B
    char* scf  = wbase + 2048;
    uint32_t sxh_u = sb + OFF_WRP + warp * WRP_SZ;

    // per-lane ldmatrix address components
    int rowA = lane & 15;
    uint32_t aOff = (uint32_t)rowA * 128;
    uint32_t aKx  = ((uint32_t)(lane >> 4)) * 16;
    uint32_t aXor = ((uint32_t)(rowA & 7)) * 16;

    int rowB = (lane & 7) + ((lane >> 4) & 1) * 8;
    uint32_t bKx  = ((uint32_t)((lane >> 3) & 1)) * 16;
    uint32_t bXor = ((uint32_t)(lane & 7)) * 16;

    int qr = lane >> 2;
    int qc = lane & 3;
    uint32_t qxor = (uint32_t)qr * 16;

    // wide-staging lane mapping
    int sc_ = lane & 7;             // 16B chunk (features sc_*8..sc_*8+7)
    int srow = lane >> 3;           // row offset within 4-row pass

    int ngrp = (E + 15) >> 4;
    int gwid = blockIdx.x * 8 + warp;
    int nwrp = gridDim.x * 8;

    // prefetch state for the upcoming tile
    uint4 pv0, pv1, pv2, pv3;
    int pg0 = 0, pglast = 0;

    // prologue prefetch
    if (gwid < ngrp) {
        int e0 = gwid << 4;
        const uint4* xin4 = (const uint4*)(g_xh + (size_t)e0 * 64);
        int r0 = srow, r1 = 4 + srow, r2 = 8 + srow, r3 = 12 + srow;
        pv0 = (e0 + r0 < E) ? xin4[r0 * 8 + sc_] : make_uint4(0, 0, 0, 0);
        pv1 = (e0 + r1 < E) ? xin4[r1 * 8 + sc_] : make_uint4(0, 0, 0, 0);
        pv2 = (e0 + r2 < E) ? xin4[r2 * 8 + sc_] : make_uint4(0, 0, 0, 0);
        pv3 = (e0 + r3 < E) ? xin4[r3 * 8 + sc_] : make_uint4(0, 0, 0, 0);
        pg0 = __ldg(bh + e0);
        pglast = __ldg(bh + min(e0 + 15, E - 1));
    }

    for (int grp = gwid; grp < ngrp; grp += nwrp) {
        int e0 = grp << 4;
        __syncwarp();

        // ---- stage from prefetched registers ----
        if (pg0 == pglast) {
            // fast path: whole tile one graph — compute cf directly
            const float4* st = (const float4*)(g_segmr + (size_t)pg0 * 64 + sc_ * 8);
            float4 s01 = st[0], s23 = st[1], s45 = st[2], s67 = st[3];
            uint4 vv[4] = { pv0, pv1, pv2, pv3 };
#pragma unroll
            for (int p = 0; p < 4; p++) {
                int row = p * 4 + srow;
                float xv[8];
                h2x4_to_f8(vv[p], xv);
                uint4 cfv;
                cfv.x = pack_h2(__expf(xv[0] - s01.x) * s01.y, __expf(xv[1] - s01.z) * s01.w);
                cfv.y = pack_h2(__expf(xv[2] - s23.x) * s23.y, __expf(xv[3] - s23.z) * s23.w);
                cfv.z = pack_h2(__expf(xv[4] - s45.x) * s45.y, __expf(xv[5] - s45.z) * s45.w);
                cfv.w = pack_h2(__expf(xv[6] - s67.x) * s67.y, __expf(xv[7] - s67.z) * s67.w);
                uint32_t off = (uint32_t)row * 128 +
                               (((uint32_t)sc_ * 16) ^ (((uint32_t)(row & 7)) * 16));
                *(uint4*)(sxh + off) = vv[p];
                *(uint4*)(scf + off) = cfv;
            }
        } else {
            // slow path: write xh tiles first, then per-edge cf from smem
            uint4 vv[4] = { pv0, pv1, pv2, pv3 };
#pragma unroll
            for (int p = 0; p < 4; p++) {
                int row = p * 4 + srow;
                uint32_t off = (uint32_t)row * 128 +
                               (((uint32_t)sc_ * 16) ^ (((uint32_t)(row & 7)) * 16));
                *(uint4*)(sxh + off) = vv[p];
            }
            __syncwarp();
#pragma unroll 4
            for (int it = 0; it < 16; it++) {
                int e = e0 + it;
                uint32_t off = (uint32_t)it * 128 + (((uint32_t)lane * 4) ^ (((uint32_t)it & 7) * 16));
                if (e < E) {
                    int g = __ldg(bh + e);
                    __half2 xh2 = *(__half2*)(sxh + off);
                    float2 xv = __half22float2(xh2);
                    float4 mr = *(const float4*)(g_segmr + (size_t)g * 64 + 2 * lane);
                    float cfa = __expf(xv.x - mr.x) * mr.y;
                    float cfb = __expf(xv.y - mr.z) * mr.w;
                    *(__half2*)(scf + off) = __floats2half2_rn(cfa, cfb);
                } else {
                    *(__half2*)(scf + off) = __floats2half2_rn(0.f, 0.f);
                }
            }
        }
        __syncwarp();

        // ---- issue prefetch for next tile (hidden under the GEMM phase) ----
        int nxt = grp + nwrp;
        if (nxt < ngrp) {
            int ne0 = nxt << 4;
            const uint4* xin4 = (const uint4*)(g_xh + (size_t)ne0 * 64);
            int r0 = srow, r1 = 4 + srow, r2 = 8 + srow, r3 = 12 + srow;
            pv0 = (ne0 + r0 < E) ? xin4[r0 * 8 + sc_] : make_uint4(0, 0, 0, 0);
            pv1 = (ne0 + r1 < E) ? xin4[r1 * 8 + sc_] : make_uint4(0, 0, 0, 0);
            pv2 = (ne0 + r2 < E) ? xin4[r2 * 8 + sc_] : make_uint4(0, 0, 0, 0);
            pv3 = (ne0 + r3 < E) ? xin4[r3 * 8 + sc_] : make_uint4(0, 0, 0, 0);
            pg0 = __ldg(bh + ne0);
            pglast = __ldg(bh + min(ne0 + 15, E - 1));
        }

        float d[8][4];
        uint32_t axh[4][4];    // A-frags of xh (k 0..63), reused by GEMM1+GEMM2
        uint32_t ax2[4][4];    // A-frags of xhh (GEMM2 k 64..127), then o1 (GEMM3)

        // ================= GEMM1: D = xh @ weight =================
#pragma unroll
        for (int j = 0; j < 8; j++) { d[j][0] = 0.f; d[j][1] = 0.f; d[j][2] = 0.f; d[j][3] = 0.f; }
#pragma unroll
        for (int kt = 0; kt < 4; kt++) {
            ldsm4(axh[kt][0], axh[kt][1], axh[kt][2], axh[kt][3],
                  sxh_u + aOff + (((uint32_t)kt * 32 + aKx) ^ aXor));
#pragma unroll
            for (int jt = 0; jt < 4; jt++) {
                uint32_t b0, b1, b2, b3;
                uint32_t baddr = sb + OFF_WT + (uint32_t)(jt * 16 + rowB) * 128
                               + (((uint32_t)kt * 32 + bKx) ^ bXor);
                ldsm4(b0, b1, b2, b3, baddr);
                mma_f16(d[2 * jt],     axh[kt][0], axh[kt][1], axh[kt][2], axh[kt][3], b0, b1);
                mma_f16(d[2 * jt + 1], axh[kt][0], axh[kt][1], axh[kt][2], axh[kt][3], b2, b3);
            }
        }
        // epi1 (in registers): xhh = cf * relu(D) -> A-frags for GEMM2 k 64..127
#pragma unroll
        for (int kt = 0; kt < 4; kt++) {
            int j0 = 2 * kt, j1 = j0 + 1;
            uint32_t o00 = (uint32_t)qr * 128 + (((uint32_t)(j0 * 16 + qc * 4)) ^ qxor);
            uint32_t o10 = (uint32_t)qr * 128 + (((uint32_t)(j1 * 16 + qc * 4)) ^ qxor);
            float2 cfa = __half22float2(*(__half2*)(scf + o00));
            float2 cfb = __half22float2(*(__half2*)(scf + o00 + 1024));
            float2 cfc = __half22float2(*(__half2*)(scf + o10));
            float2 cfd = __half22float2(*(__half2*)(scf + o10 + 1024));
            ax2[kt][0] = pack_h2(fmaxf(d[j0][0], 0.f) * cfa.x, fmaxf(d[j0][1], 0.f) * cfa.y);
            ax2[kt][1] = pack_h2(fmaxf(d[j0][2], 0.f) * cfb.x, fmaxf(d[j0][3], 0.f) * cfb.y);
            ax2[kt][2] = pack_h2(fmaxf(d[j1][0], 0.f) * cfc.x, fmaxf(d[j1][1], 0.f) * cfc.y);
            ax2[kt][3] = pack_h2(fmaxf(d[j1][2], 0.f) * cfd.x, fmaxf(d[j1][3], 0.f) * cfd.y);
        }

        // ================= GEMM2: D = [xh | xhh] @ V1 =================
#pragma unroll
        for (int j = 0; j < 8; j++) { d[j][0] = 0.f; d[j][1] = 0.f; d[j][2] = 0.f; d[j][3] = 0.f; }
#pragma unroll
        for (int kt = 0; kt < 8; kt++) {
            const uint32_t* a = (kt < 4) ? axh[kt] : ax2[kt - 4];
#pragma unroll
            for (int jt = 0; jt < 4; jt++) {
                uint32_t b0, b1, b2, b3;
                uint32_t baddr = sb + OFF_V1 + (uint32_t)(jt * 16 + rowB) * 256
                               + (((uint32_t)kt * 32 + bKx) ^ bXor);
                ldsm4(b0, b1, b2, b3, baddr);
                mma_f16(d[2 * jt],     a[0], a[1], a[2], a[3], b0, b1);
                mma_f16(d[2 * jt + 1], a[0], a[1], a[2], a[3], b2, b3);
            }
        }
        // epi2 (in registers): o1 = relu(D + c1) -> A-frags for GEMM3
#pragma unroll
        for (int kt = 0; kt < 4; kt++) {
            int j0 = 2 * kt, j1 = j0 + 1;
            float2 bv0 = *(const float2*)(sc1 + j0 * 8 + qc * 2);
            float2 bv1 = *(const float2*)(sc1 + j1 * 8 + qc * 2);
            ax2[kt][0] = pack_h2(fmaxf(d[j0][0] + bv0.x, 0.f), fmaxf(d[j0][1] + bv0.y, 0.f));
            ax2[kt][1] = pack_h2(fmaxf(d[j0][2] + bv0.x, 0.f), fmaxf(d[j0][3] + bv0.y, 0.f));
            ax2[kt][2] = pack_h2(fmaxf(d[j1][0] + bv1.x, 0.f), fmaxf(d[j1][1] + bv1.y, 0.f));
            ax2[kt][3] = pack_h2(fmaxf(d[j1][2] + bv1.x, 0.f), fmaxf(d[j1][3] + bv1.y, 0.f));
        }

        // ================= GEMM3: D = o1 @ V2 =================
#pragma unroll
        for (int j = 0; j < 8; j++) { d[j][0] = 0.f; d[j][1] = 0.f; d[j][2] = 0.f; d[j][3] = 0.f; }
#pragma unroll
        for (int kt = 0; kt < 4; kt++) {
#pragma unroll
            for (int jt = 0; jt < 4; jt++) {
                uint32_t b0, b1, b2, b3;
                uint32_t baddr = sb + OFF_V2 + (uint32_t)(jt * 16 + rowB) * 128
                               + (((uint32_t)kt * 32 + bKx) ^ bXor);
                ldsm4(b0, b1, b2, b3, baddr);
                mma_f16(d[2 * jt],     ax2[kt][0], ax2[kt][1], ax2[kt][2], ax2[kt][3], b0, b1);
                mma_f16(d[2 * jt + 1], ax2[kt][0], ax2[kt][1], ax2[kt][2], ax2[kt][3], b2, b3);
            }
        }
        // epi3: o2 = relu(D + c2); z = o2 . V3 + c3; out = sigmoid(z)
        float zlo = 0.f, zhi = 0.f;
#pragma unroll
        for (int j = 0; j < 8; j++) {
            int col = j * 8 + qc * 2;
            float2 bv = *(const float2*)(sc2 + col);
            float2 wv = *(const float2*)(sV3 + col);
            zlo = fmaf(fmaxf(d[j][0] + bv.x, 0.f), wv.x, zlo);
            zlo = fmaf(fmaxf(d[j][1] + bv.y, 0.f), wv.y, zlo);
            zhi = fmaf(fmaxf(d[j][2] + bv.x, 0.f), wv.x, zhi);
            zhi = fmaf(fmaxf(d[j][3] + bv.y, 0.f), wv.y, zhi);
        }
        zlo += __shfl_xor_sync(0xffffffffu, zlo, 1);
        zlo += __shfl_xor_sync(0xffffffffu, zlo, 2);
        zhi += __shfl_xor_sync(0xffffffffu, zhi, 1);
        zhi += __shfl_xor_sync(0xffffffffu, zhi, 2);
        if (qc == 0) {
            int ea = e0 + qr, eb = e0 + qr + 8;
            if (ea < E) out[ea] = 1.f / (1.f + __expf(-(zlo + c3v)));
            if (eb < E) out[eb] = 1.f / (1.f + __expf(-(zhi + c3v)));
        }
    }
}

// ---------------------------------------------------------------------------
// kernel_launch
// ---------------------------------------------------------------------------
extern "C" void kernel_launch(void* const* d_in, const int* in_sizes, int n_in,
                              void* d_out, int out_size)
{
    const float* x     = (const float*)d_in[0];
    const float* u     = (const float*)d_in[1];
    const int*   batch = (const int*)d_in[2];
    const int*   hidx  = (const int*)d_in[3];
    const int*   bh    = (const int*)d_in[4];

    int N = in_sizes[0] / 6;
    int G = in_sizes[1] / 4;
    int E = in_sizes[4];

    int wb = (in_sizes[5] == 1) ? 6 : 5;   // skip scalar "r" if present
    const float* W1 = (const float*)d_in[wb + 0];
    const float* b1 = (const float*)d_in[wb + 1];
    const float* W2 = (const float*)d_in[wb + 2];
    const float* b2 = (const float*)d_in[wb + 3];
    const float* W3 = (const float*)d_in[wb + 4];
    const float* b3 = (const float*)d_in[wb + 5];
    const float* Wt = (const float*)d_in[wb + 6];
    const float* V1 = (const float*)d_in[wb + 7];
    const float* c1 = (const float*)d_in[wb + 8];
    const float* V2 = (const float*)d_in[wb + 9];
    const float* c2 = (const float*)d_in[wb + 10];
    const float* V3 = (const float*)d_in[wb + 11];
    const float* c3 = (const float*)d_in[wb + 12];

    int writeBatch = (out_size >= 2 * E) ? 1 : 0;

    cudaFuncSetAttribute(k_node_mlp_mma, cudaFuncAttributeMaxDynamicSharedMemorySize, K1_SMEM);
    k_node_mlp_mma<<<(N + 255) / 256, 512, K1_SMEM>>>(x, u, batch, W1, b1, W2, b2, W3, b3, N);

    k_segstats<<<G, 512>>>(hidx, bh, E, (float*)d_out, writeBatch);

    int nsm = 148;
    cudaDeviceGetAttribute(&nsm, cudaDevAttrMultiProcessorCount, 0);
    cudaFuncSetAttribute(k_main_mma, cudaFuncAttributeMaxDynamicSharedMemorySize, SMEM_MAIN);
    k_main_mma<<<nsm * 2, 256, SMEM_MAIN>>>(bh, Wt, V1, c1, V2, c2, V3, c3,
                                            (float*)d_out, E);
}